// round 14
// baseline (speedup 1.0000x reference)
#include <cuda_runtime.h>
#include <cuda_fp16.h>
#include <math.h>
#include <stdint.h>

#define NB 8
#define NT 8192
#define ND 128
#define NH 8
#define TILE 64
#define NTILES 128             // NT / TILE
#define NGRP 2                 // partial groups per block

// ---------------- scratch (device globals; no allocs allowed) ---------------
static __device__ float g_part[NB * NTILES * NGRP * 2048];  // ctx partials
static __device__ float g_partk[NB * NTILES * NGRP * 128];  // ksum partials
static __device__ float g_ctx[NB * 2048];                   // [b][h][d][e]
static __device__ float g_ksum[NB * 128];                   // [b][h*16+d]
static __device__ __half g_wt[4][16384];                    // W tiles (fp16, swizzled)
static __device__ float g_rope[NT * 16];                    // [t][j*2]=sin, [j*2+1]=cos

// ---------------------------------------------------------------------------
__device__ __forceinline__ void mma16816(float c[4], const uint32_t a[4],
                                         uint32_t b0, uint32_t b1) {
    asm volatile(
        "mma.sync.aligned.m16n8k16.row.col.f32.f16.f16.f32 "
        "{%0,%1,%2,%3}, {%4,%5,%6,%7}, {%8,%9}, {%0,%1,%2,%3};"
        : "+f"(c[0]), "+f"(c[1]), "+f"(c[2]), "+f"(c[3])
        : "r"(a[0]), "r"(a[1]), "r"(a[2]), "r"(a[3]), "r"(b0), "r"(b1));
}
__device__ __forceinline__ void ldsm4(uint32_t r[4], uint32_t addr) {
    asm volatile("ldmatrix.sync.aligned.m8n8.x4.shared.b16 {%0,%1,%2,%3}, [%4];"
                 : "=r"(r[0]), "=r"(r[1]), "=r"(r[2]), "=r"(r[3]) : "r"(addr));
}
__device__ __forceinline__ uint32_t smem_u32(const void* p) {
    return (uint32_t)__cvta_generic_to_shared(p);
}
__device__ __forceinline__ void cp_async16(uint32_t dst, const void* src) {
    asm volatile("cp.async.cg.shared.global [%0], [%1], 16;" :: "r"(dst), "l"(src));
}
#define CP_COMMIT() asm volatile("cp.async.commit_group;" ::: "memory")
#define CP_WAIT(n)  asm volatile("cp.async.wait_group %0;" :: "n"(n) : "memory")

// A tile layout: [rows][128 fp16 = 256B], 16B-granule XOR swizzle:
// phys_byte = row*256 + (((k>>3) ^ (row&7))<<4) + (k&7)*2.

// Stage one granule (8 consecutive k) of x: 2 float4 -> 8 fp16 (one 16B store).
__device__ __forceinline__ void x_store8(char* a, int row, int k8, float4 v0, float4 v1) {
    uint32_t off = (uint32_t)(row * 256 + ((k8 ^ (row & 7)) << 4));
    __half2 h[4];
    h[0] = __floats2half2_rn(v0.x, v0.y);
    h[1] = __floats2half2_rn(v0.z, v0.w);
    h[2] = __floats2half2_rn(v1.x, v1.y);
    h[3] = __floats2half2_rn(v1.z, v1.w);
    *(uint4*)(a + off) = *(const uint4*)h;
}
__device__ __forceinline__ void a_store4(char* a, int row, int k4, float4 v) {
    uint32_t off = (uint32_t)(row * 256 + ((((k4 >> 1) ^ (row & 7)) << 4) | ((k4 & 1) << 3)));
    *(__half2*)(a + off)     = __floats2half2_rn(v.x, v.y);
    *(__half2*)(a + off + 4) = __floats2half2_rn(v.z, v.w);
}

// Issue both 16KB W chunks of one W tile (two commit groups).
__device__ __forceinline__ void issue_w2(const __half* __restrict__ wsrc,
                                         uint32_t wB, int tid) {
    #pragma unroll
    for (int half = 0; half < 2; half++) {
        const char* src = (const char*)wsrc + half * 128;
        uint32_t buf = wB + (uint32_t)half * 16384;
        #pragma unroll
        for (int l = 0; l < 4; l++) {
            int i = tid + l * 256;
            int n = i >> 3, j = i & 7;
            cp_async16(buf + (uint32_t)i * 16, src + n * 256 + j * 16);
        }
        CP_COMMIT();
    }
}

// Compute 4 global ksteps (ks = half*4 + ksl): acc += A @ Wchunk.
__device__ __forceinline__ void gemm_chunk(uint32_t aT, uint32_t wbuf, int half,
                                           float acc[2][4][4], int r0, int c0, int lane) {
    const int l7 = lane & 7;
    const int am8 = ((lane >> 3) & 1) << 3;
    const int akh = lane >> 4;
    const int bm8 = ((lane >> 4) & 1) << 3;
    const int bpar = (lane >> 3) & 1;
    uint32_t arow[2], brow[2];
    int arow7[2], brow7[2];
    #pragma unroll
    for (int mt = 0; mt < 2; mt++) {
        int r = r0 + mt * 16 + am8 + l7;
        arow[mt] = (uint32_t)(r * 256); arow7[mt] = r & 7;
    }
    #pragma unroll
    for (int n2 = 0; n2 < 2; n2++) {
        int r = c0 + n2 * 16 + bm8 + l7;
        brow[n2] = (uint32_t)(r * 128); brow7[n2] = r & 7;
    }
    #pragma unroll
    for (int ksl = 0; ksl < 4; ksl++) {
        int ks = half * 4 + ksl;
        uint32_t Af[2][4], Bf[2][4];
        #pragma unroll
        for (int mt = 0; mt < 2; mt++) {
            uint32_t g = (uint32_t)(((2 * ks + akh) ^ arow7[mt]) << 4);
            ldsm4(Af[mt], aT + arow[mt] + g);
        }
        #pragma unroll
        for (int n2 = 0; n2 < 2; n2++) {
            uint32_t g = (uint32_t)(((2 * ksl + bpar) ^ brow7[n2]) << 4);
            ldsm4(Bf[n2], wbuf + brow[n2] + g);
        }
        #pragma unroll
        for (int n2 = 0; n2 < 2; n2++)
            #pragma unroll
            for (int j = 0; j < 2; j++) {
                int nt = n2 * 2 + j;
                uint32_t b0 = Bf[n2][j * 2], b1 = Bf[n2][j * 2 + 1];
                #pragma unroll
                for (int mt = 0; mt < 2; mt++)
                    mma16816(acc[mt][nt], Af[mt], b0, b1);
            }
    }
}

// Full GEMM from pre-issued chunks: waits chunk-by-chunk, computes.
__device__ __forceinline__ void gemm_go(uint32_t aT, uint32_t wB, float acc[2][4][4],
                                        int r0, int c0, int lane) {
    #pragma unroll
    for (int mt = 0; mt < 2; mt++)
        #pragma unroll
        for (int nt = 0; nt < 4; nt++)
            #pragma unroll
            for (int i = 0; i < 4; i++) acc[mt][nt][i] = 0.f;
    CP_WAIT(1);
    __syncthreads();
    gemm_chunk(aT, wB, 0, acc, r0, c0, lane);
    CP_WAIT(0);
    __syncthreads();
    gemm_chunk(aT, wB + 16384, 1, acc, r0, c0, lane);
}

// bias + RoPE + elu+1 on accumulators.
__device__ __forceinline__ void rope_elu_acc(float acc[2][4][4],
                                             const float* bias_s, int c0, int tg,
                                             const float sn[4][2], const float cs[4][2]) {
    #pragma unroll
    for (int mt = 0; mt < 2; mt++)
        #pragma unroll
        for (int t = 0; t < 2; t++)
            #pragma unroll
            for (int i = 0; i < 4; i++) {
                int ridx = mt * 2 + (i >> 1);
                int jj = i & 1;
                float x1 = acc[mt][2 * t][i]     + bias_s[c0 + t * 16 + tg * 2 + jj];
                float x2 = acc[mt][2 * t + 1][i] + bias_s[c0 + t * 16 + 8 + tg * 2 + jj];
                float s = sn[ridx][jj], c = cs[ridx][jj];
                float y1 = x1 * c - x2 * s;
                float y2 = x1 * s + x2 * c;
                acc[mt][2 * t][i]     = y1 > 0.f ? y1 + 1.f : __expf(y1);
                acc[mt][2 * t + 1][i] = y2 > 0.f ? y2 + 1.f : __expf(y2);
            }
}

// Store accumulators as fp16 tile [rows][128 fp16], 16B-granule swizzle.
__device__ __forceinline__ void acc_storeH(char* dstH, const float acc[2][4][4],
                                           int r0, int c0, int qid, int tg) {
    #pragma unroll
    for (int mt = 0; mt < 2; mt++)
        #pragma unroll
        for (int nt = 0; nt < 4; nt++)
            #pragma unroll
            for (int h2 = 0; h2 < 2; h2++) {
                int row = r0 + mt * 16 + h2 * 8 + qid;
                int col = c0 + nt * 8 + tg * 2;
                uint32_t off = (uint32_t)(row * 256 +
                    (((col >> 3) ^ (row & 7)) << 4) + (col & 7) * 2);
                *(__half2*)(dstH + off) =
                    __floats2half2_rn(acc[mt][nt][h2 * 2], acc[mt][nt][h2 * 2 + 1]);
            }
}

// Store accumulators TRANSPOSED as fp16: dstT[feature][t], rows 128B,
// phys = f*128 + (((t>>3) ^ (f&7))<<4) + (t&7)*2.
__device__ __forceinline__ void acc_storeT(char* dstT, const float acc[2][4][4],
                                           const float* bias_s, bool add_bias,
                                           int r0, int c0, int qid, int tg) {
    #pragma unroll
    for (int mt = 0; mt < 2; mt++)
        #pragma unroll
        for (int nt = 0; nt < 4; nt++)
            #pragma unroll
            for (int i = 0; i < 4; i++) {
                int t = r0 + mt * 16 + (i >> 1) * 8 + qid;
                int f = c0 + nt * 8 + tg * 2 + (i & 1);
                float v = acc[mt][nt][i];
                if (add_bias) v += bias_s[f];
                uint32_t off = (uint32_t)(f * 128 + (((t >> 3) ^ (f & 7)) << 4) + (t & 7) * 2);
                *(__half*)(dstT + off) = __float2half_rn(v);
            }
}

// Load rope tables from global.
__device__ __forceinline__ void load_rope(int t0, int r0, int qid, int tg,
                                          float sn[4][2], float cs[4][2]) {
    #pragma unroll
    for (int ridx = 0; ridx < 4; ridx++) {
        int mt = ridx >> 1, half = ridx & 1;
        int t = t0 + r0 + mt * 16 + half * 8 + qid;
        float4 v = *(const float4*)&g_rope[t * 16 + tg * 4];
        sn[ridx][0] = v.x; cs[ridx][0] = v.y;
        sn[ridx][1] = v.z; cs[ridx][1] = v.w;
    }
}

// ---------------------------------------------------------------------------
// Kernel 0: setup. Blocks 0-3: W->fp16 swizzled; blocks 4-35: rope tables.
// ---------------------------------------------------------------------------
extern "C" __global__ void __launch_bounds__(256)
la_setup(const float* __restrict__ Wq, const float* __restrict__ Wk,
         const float* __restrict__ Wv, const float* __restrict__ Wo)
{
    if (blockIdx.x < 4) {
        const float* W = (blockIdx.x == 0) ? Wk : (blockIdx.x == 1) ? Wq
                       : (blockIdx.x == 2) ? Wv : Wo;
        __half* wh = g_wt[blockIdx.x];
        const float4* Wp = (const float4*)W;
        for (int i = threadIdx.x; i < 4096; i += 256) {
            int k = i >> 5, n4 = i & 31;
            float4 w = Wp[i];
            float vv[4] = {w.x, w.y, w.z, w.w};
            #pragma unroll
            for (int u = 0; u < 4; u++) {
                int n = n4 * 4 + u;
                uint32_t e = (uint32_t)(n * 128 + ((((k >> 3) ^ (n & 7)) << 3) | (k & 7)));
                wh[e] = __float2half_rn(vv[u]);
            }
        }
    } else {
        const float invf[8] = {1.0f, 0.31622776601683794f, 0.1f, 0.03162277660168379f,
                               0.01f, 0.0031622776601683794f, 0.001f, 0.00031622776601683794f};
        int t = (blockIdx.x - 4) * 256 + threadIdx.x;     // 32 blocks x 256 = 8192
        float tf = (float)t;
        #pragma unroll
        for (int j = 0; j < 8; j++) {
            float s, c;
            sincosf(tf * invf[j], &s, &c);
            g_rope[t * 16 + j * 2] = s;
            g_rope[t * 16 + j * 2 + 1] = c;
        }
    }
}

// ---------------------------------------------------------------------------
// Kernel 1: K, V GEMMs; transposed fp16 k/v tiles; ctx via diagonal MMA.
// smem: A/vT 16K | Wbuf 32K | kT 16K | bias 1K  (~65.5K -> 3 blocks/SM)
// ---------------------------------------------------------------------------
#define KV_WB    16384
#define KV_KT    49152
#define KV_BIAS  65536
#define KV_SMEM  66560

extern "C" __global__ void __launch_bounds__(256, 3)
la_kv(const float* __restrict__ x,
      const float* __restrict__ bk, const float* __restrict__ bv)
{
    extern __shared__ char sm[];
    char* A_t = sm;
    char* kT  = sm + KV_KT;
    char* vT  = sm;                         // alias A (A dead after V GEMM)
    float* bias_s = (float*)(sm + KV_BIAS); // [2][128]: k, v

    const int tid = threadIdx.x;
    const int lane = tid & 31;
    const int wid = tid >> 5;
    const int qid = lane >> 2, tg = lane & 3;
    const int r0 = (wid & 1) * 32;
    const int c0 = (wid >> 1) * 32;
    const int b  = blockIdx.y;
    const int t0 = blockIdx.x * TILE;

    const uint32_t aT  = smem_u32(A_t);
    const uint32_t wB  = smem_u32(sm + KV_WB);
    const uint32_t kTa = smem_u32(kT);
    const uint32_t vTa = aT;

    issue_w2(g_wt[0], wB, tid);             // Wk in flight under x load

    const float4* xp = (const float4*)(x + ((size_t)(b * NT + t0)) * ND);
    for (int i = tid; i < 1024; i += 256) {
        int row = i >> 4, k8 = i & 15;
        x_store8(A_t, row, k8, xp[row * 32 + k8 * 2], xp[row * 32 + k8 * 2 + 1]);
    }
    if (tid < 128) {
        bias_s[tid]       = bk[tid];
        bias_s[128 + tid] = bv[tid];
    }
    float sn[4][2], cs[4][2];
    load_rope(t0, r0, qid, tg, sn, cs);

    float acc[2][4][4];

    // ---- K GEMM (first sync inside gemm_go also publishes A stores) ----
    gemm_go(aT, wB, acc, r0, c0, lane);
    __syncthreads();                        // all Wbuf reads done
    issue_w2(g_wt[2], wB, tid);             // Wv in flight under K epilogue
    rope_elu_acc(acc, bias_s, c0, tg, sn, cs);

    // ksum partials via register shuffles (rows r0..r0+31 per warp)
    {
        float s[8];
        #pragma unroll
        for (int nt = 0; nt < 4; nt++)
            #pragma unroll
            for (int j = 0; j < 2; j++) {
                float v = 0.f;
                #pragma unroll
                for (int mt = 0; mt < 2; mt++)
                    #pragma unroll
                    for (int h2 = 0; h2 < 2; h2++)
                        v += acc[mt][nt][h2 * 2 + j];
                s[nt * 2 + j] = v;
            }
        #pragma unroll
        for (int off = 4; off <= 16; off <<= 1)
            #pragma unroll
            for (int u = 0; u < 8; u++)
                s[u] += __shfl_xor_sync(0xffffffffu, s[u], off);
        if (qid == 0) {
            size_t slot = ((size_t)(b * NTILES + blockIdx.x) * NGRP + (wid & 1));
            #pragma unroll
            for (int nt = 0; nt < 4; nt++)
                #pragma unroll
                for (int j = 0; j < 2; j++)
                    g_partk[slot * 128 + c0 + nt * 8 + tg * 2 + j] = s[nt * 2 + j];
        }
    }
    acc_storeT(kT, acc, bias_s, false, r0, c0, qid, tg);

    // ---- V GEMM ----
    gemm_go(aT, wB, acc, r0, c0, lane);
    __syncthreads();                        // all A reads done before vT overwrite
    acc_storeT(vT, acc, bias_s + 128, true, r0, c0, qid, tg);
    __syncthreads();                        // kT + vT visible

    // ---- ctx via diagonal MMA: warp = (tile = wid&3, tgrp = wid>>2) ----
    {
        const int tile = wid & 3, tgrp = wid >> 2;
        const int base = tile * 32;
        const int l7 = lane & 7;
        const int am8 = ((lane >> 3) & 1) << 3;
        const int akh = lane >> 4;
        const int bm8 = ((lane >> 4) & 1) << 3;
        const int bpar = (lane >> 3) & 1;
        float c2[2][4][4];
        #pragma unroll
        for (int mt = 0; mt < 2; mt++)
            #pragma unroll
            for (int nt = 0; nt < 4; nt++)
                #pragma unroll
                for (int i = 0; i < 4; i++) c2[mt][nt][i] = 0.f;

        #pragma unroll
        for (int ksl = 0; ksl < 2; ksl++) {
            uint32_t Af[2][4], Bf[2][4];
            #pragma unroll
            for (int mt = 0; mt < 2; mt++) {
                int r = base + mt * 16 + am8 + l7;
                uint32_t g = (uint32_t)(((tgrp * 4 + 2 * ksl + akh) ^ (r & 7)) << 4);
                ldsm4(Af[mt], kTa + (uint32_t)(r * 128) + g);
            }
            #pragma unroll
            for (int n2 = 0; n2 < 2; n2++) {
                int r = base + n2 * 16 + bm8 + l7;
                uint32_t g = (uint32_t)(((tgrp * 4 + 2 * ksl + bpar) ^ (r & 7)) << 4);
                ldsm4(Bf[n2], vTa + (uint32_t)(r * 128) + g);
            }
            #pragma unroll
            for (int n2 = 0; n2 < 2; n2++)
                #pragma unroll
                for (int j = 0; j < 2; j++) {
                    int nt = n2 * 2 + j;
                    uint32_t b0 = Bf[n2][j * 2], b1 = Bf[n2][j * 2 + 1];
                    #pragma unroll
                    for (int mt = 0; mt < 2; mt++)
                        mma16816(c2[mt][nt], Af[mt], b0, b1);
                }
        }

        // keep diagonal blocks: mt == nt>>1
        size_t slot = ((size_t)(b * NTILES + blockIdx.x) * NGRP + tgrp);
        float* pp = g_part + slot * 2048;
        #pragma unroll
        for (int mt = 0; mt < 2; mt++)
            #pragma unroll
            for (int n1 = 0; n1 < 2; n1++) {
                int nt = mt * 2 + n1;
                #pragma unroll
                for (int i = 0; i < 4; i++) {
                    int head = tile * 2 + mt;
                    int d = (i >> 1) * 8 + qid;
                    int e = n1 * 8 + tg * 2 + (i & 1);
                    pp[head * 256 + d * 16 + e] = c2[mt][nt][i];
                }
            }
    }
}

// ---------------------------------------------------------------------------
// Kernel 2: reduce partials. grid = NB*8 blocks, 256 threads.
// ---------------------------------------------------------------------------
extern "C" __global__ void __launch_bounds__(256)
la_red()
{
    int b = blockIdx.x >> 3, ch = blockIdx.x & 7;
    int e = ch * 256 + threadIdx.x;
    const float* pc = g_part + (size_t)b * NTILES * NGRP * 2048;
    float s0 = 0.f, s1 = 0.f, s2 = 0.f, s3 = 0.f;
    for (int j = 0; j < NTILES * NGRP; j += 4) {
        s0 += pc[(size_t)j * 2048 + e];
        s1 += pc[(size_t)(j + 1) * 2048 + e];
        s2 += pc[(size_t)(j + 2) * 2048 + e];
        s3 += pc[(size_t)(j + 3) * 2048 + e];
    }
    g_ctx[b * 2048 + e] = (s0 + s1) + (s2 + s3);
    if (ch == 0 && threadIdx.x < 128) {
        const float* pk = g_partk + (size_t)b * NTILES * NGRP * 128;
        float k0 = 0.f, k1 = 0.f, k2 = 0.f, k3 = 0.f;
        for (int j = 0; j < NTILES * NGRP; j += 4) {
            k0 += pk[(size_t)j * 128 + threadIdx.x];
            k1 += pk[(size_t)(j + 1) * 128 + threadIdx.x];
            k2 += pk[(size_t)(j + 2) * 128 + threadIdx.x];
            k3 += pk[(size_t)(j + 3) * 128 + threadIdx.x];
        }
        g_ksum[b * 128 + threadIdx.x] = (k0 + k1) + (k2 + k3);
    }
}

// ---------------------------------------------------------------------------
// Kernel 3: q = rope_elu(x@Wq+bq); attn = (q@ctxBD)*z (MMA); out = attn@Wo+bo.
// smem: A 16K | Wbuf 32K | z 2.3K | ksum .5K | bias 1K  (~52K -> 3 blocks/SM)
// ---------------------------------------------------------------------------
#define QO_WB    16384
#define QO_Z     49152
#define QO_KSUM  51456
#define QO_BIAS  51968
#define QO_SMEM  52992

extern "C" __global__ void __launch_bounds__(256, 3)
la_qout(const float* __restrict__ x,
        const float* __restrict__ bq, const float* __restrict__ bo,
        float* __restrict__ out)
{
    extern __shared__ char sm[];
    char* A_t  = sm;
    char* Wbuf = sm + QO_WB;
    float* z_s    = (float*)(sm + QO_Z);     // [64][9] padded
    float* ksum_s = (float*)(sm + QO_KSUM);
    float* bias_s = (float*)(sm + QO_BIAS);  // [2][128]: q, o

    const int tid = threadIdx.x;
    const int lane = tid & 31;
    const int wid = tid >> 5;
    const int qid = lane >> 2, tg = lane & 3;
    const int r0 = (wid & 1) * 32;
    const int c0 = (wid >> 1) * 32;
    const int hA = c0 >> 4;                  // first head of this warp's columns
    const int b  = blockIdx.y;
    const int t0 = blockIdx.x * TILE;

    const uint32_t aT = smem_u32(A_t);
    const uint32_t wB = smem_u32(Wbuf);

    issue_w2(g_wt[1], wB, tid);             // Wq in flight under x load

    const float4* xp = (const float4*)(x + ((size_t)(b * NT + t0)) * ND);
    for (int i = tid; i < 1024; i += 256) {
        int row = i >> 4, k8 = i & 15;
        x_store8(A_t, row, k8, xp[row * 32 + k8 * 2], xp[row * 32 + k8 * 2 + 1]);
    }
    if (tid < 128) {
        ksum_s[tid] = g_ksum[b * 128 + tid];
        bias_s[tid] = bq[tid];
        bias_s[128 + tid] = bo[tid];
    }
    float sn[4][2], cs[4][2];
    load_rope(t0, r0, qid, tg, sn, cs);

    float acc[2][4][4];

    // ---- Q GEMM ----
    gemm_go(aT, wB, acc, r0, c0, lane);
    __syncthreads();                        // Wbuf + A reads done
    rope_elu_acc(acc, bias_s, c0, tg, sn, cs);

    // ---- z = q . ksum (from accumulators, shuffle-reduced over tg lanes) ----
    {
        float zp[2][2][2];                   // [mt][h2][g]
        #pragma unroll
        for (int mt = 0; mt < 2; mt++)
            #pragma unroll
            for (int h2 = 0; h2 < 2; h2++)
                #pragma unroll
                for (int g = 0; g < 2; g++) {
                    float s = 0.f;
                    #pragma unroll
                    for (int n1 = 0; n1 < 2; n1++) {
                        int nt = g * 2 + n1;
                        #pragma unroll
                        for (int j = 0; j < 2; j++)
                            s = fmaf(acc[mt][nt][h2 * 2 + j],
                                     ksum_s[c0 + nt * 8 + tg * 2 + j], s);
                    }
                    zp[mt][h2][g] = s;
                }
        #pragma unroll
        for (int off = 1; off <= 2; off <<= 1)
            #pragma unroll
            for (int mt = 0; mt < 2; mt++)
                #pragma unroll
                for (int h2 = 0; h2 < 2; h2++)
                    #pragma unroll
                    for (int g = 0; g < 2; g++)
                        zp[mt][h2][g] += __shfl_xor_sync(0xffffffffu, zp[mt][h2][g], off);
        if (tg == 0) {
            #pragma unroll
            for (int mt = 0; mt < 2; mt++)
                #pragma unroll
                for (int h2 = 0; h2 < 2; h2++) {
                    int row = r0 + mt * 16 + h2 * 8 + qid;
                    #pragma unroll
                    for (int g = 0; g < 2; g++)
                        z_s[row * 9 + hA + g] = zp[mt][h2][g] + 1e-6f;
                }
        }
    }

    // ---- store q into A tile (x dead); zero ctxBD region ----
    acc_storeH(A_t, acc, r0, c0, qid, tg);
    {
        uint4 zero4 = make_uint4(0, 0, 0, 0);
        for (int i = tid; i < 2048; i += 256) ((uint4*)Wbuf)[i] = zero4;
    }
    __syncthreads();                        // zeros done before diagonal fill

    // ---- fill ctxBD diagonal blocks (fp16) ----
    {
        const float* ctxg = g_ctx + b * 2048;
        for (int i = tid; i < 2048; i += 256) {
            int h = i >> 8, d = (i >> 4) & 15, e = i & 15;
            float v = ctxg[i];
            int n = h * 16 + e, kg = h * 16 + d;
            int c = kg >> 6, kl = kg & 63, gk = kl >> 3, k7 = kl & 7;
            *(__half*)(Wbuf + c * 16384 + n * 128 +
                       (((gk ^ (n & 7)) << 4) | (k7 * 2))) = __float2half_rn(v);
        }
    }
    __syncthreads();                        // q tile + ctxBD + z_s visible

    // ---- apply GEMM: attn = q @ ctxBD ----
    #pragma unroll
    for (int mt = 0; mt < 2; mt++)
        #pragma unroll
        for (int nt = 0; nt < 4; nt++)
            #pragma unroll
            for (int i = 0; i < 4; i++) acc[mt][nt][i] = 0.f;
    gemm_chunk(aT, wB, 0, acc, r0, c0, lane);
    gemm_chunk(aT, wB + 16384, 1, acc, r0, c0, lane);
    __syncthreads();                        // Wbuf + A reads done

    issue_w2(g_wt[3], wB, tid);             // Wo in flight under scale+store

    // ---- z-scale and store attn into A tile ----
    {
        float zi[2][2][2];
        #pragma unroll
        for (int mt = 0; mt < 2; mt++)
            #pragma unroll
            for (int h2 = 0; h2 < 2; h2++) {
                int row = r0 + mt * 16 + h2 * 8 + qid;
                #pragma unroll
                for (int g = 0; g < 2; g++)
                    zi[mt][h2][g] = 1.f / z_s[row * 9 + hA + g];
            }
        #pragma unroll
        for (int mt = 0; mt < 2; mt++)
            #pragma unroll
            for (int nt = 0; nt < 4; nt++) {
                int g = nt >> 1;
                #pragma unroll
                for (int h2 = 0; h2 < 2; h2++) {
                    acc[mt][nt][h2 * 2]     *= zi[mt][h2][g];
                    acc[mt][nt][h2 * 2 + 1] *= zi[mt][h2][g];
                }
            }
        acc_storeH(A_t, acc, r0, c0, qid, tg);
    }

    // ---- O GEMM (first sync inside gemm_go publishes attn stores) ----
    gemm_go(aT, wB, acc, r0, c0, lane);

    // direct global store with bias
    {
        float* op = out + ((size_t)(b * NT + t0)) * ND;
        #pragma unroll
        for (int mt = 0; mt < 2; mt++)
            #pragma unroll
            for (int nt = 0; nt < 4; nt++)
                #pragma unroll
                for (int h2 = 0; h2 < 2; h2++) {
                    int row = r0 + mt * 16 + h2 * 8 + qid;
                    int col = c0 + nt * 8 + tg * 2;
                    *(float2*)(op + (size_t)row * ND + col) =
                        make_float2(acc[mt][nt][h2 * 2] + bias_s[128 + col],
                                    acc[mt][nt][h2 * 2 + 1] + bias_s[128 + col + 1]);
                }
    }
}

// ---------------------------------------------------------------------------
extern "C" void kernel_launch(void* const* d_in, const int* in_sizes, int n_in,
                              void* d_out, int out_size)
{
    const float* x  = (const float*)d_in[0];
    const float* Wq = (const float*)d_in[1];
    const float* bq = (const float*)d_in[2];
    const float* Wk = (const float*)d_in[3];
    const float* bk = (const float*)d_in[4];
    const float* Wv = (const float*)d_in[5];
    const float* bv = (const float*)d_in[6];
    const float* Wo = (const float*)d_in[7];
    const float* bo = (const float*)d_in[8];
    float* out = (float*)d_out;

    cudaFuncSetAttribute(la_kv,   cudaFuncAttributeMaxDynamicSharedMemorySize, KV_SMEM);
    cudaFuncSetAttribute(la_qout, cudaFuncAttributeMaxDynamicSharedMemorySize, QO_SMEM);

    la_setup<<<36, 256>>>(Wq, Wk, Wv, Wo);

    dim3 grid(NT / TILE, NB);
    la_kv<<<grid, 256, KV_SMEM>>>(x, bk, bv);
    la_red<<<NB * 8, 256>>>();
    la_qout<<<grid, 256, QO_SMEM>>>(x, bq, bo, out);
}

// round 15
// speedup vs baseline: 1.0408x; 1.0408x over previous
#include <cuda_runtime.h>
#include <cuda_fp16.h>
#include <math.h>
#include <stdint.h>

#define NB 8
#define NT 8192
#define ND 128
#define NH 8
#define TILE 64
#define NTILES 128             // NT / TILE
#define NGRP 2                 // partial groups per block

// ---------------- scratch (device globals; no allocs allowed) ---------------
static __device__ float g_part[NB * NTILES * NGRP * 2048];  // ctx partials
static __device__ float g_partk[NB * NTILES * NGRP * 128];  // ksum partials
static __device__ float g_ksum[NB * 128];                   // [b][h*16+d]
static __device__ __half g_wt[4][16384];                    // W tiles (fp16, swizzled)
static __device__ __half g_ctxBD[NB][16384];                // block-diag ctx (fp16, swizzled)
static __device__ float g_rope[NT * 16];                    // [t][j*2]=sin, [j*2+1]=cos

// ---------------------------------------------------------------------------
__device__ __forceinline__ void mma16816(float c[4], const uint32_t a[4],
                                         uint32_t b0, uint32_t b1) {
    asm volatile(
        "mma.sync.aligned.m16n8k16.row.col.f32.f16.f16.f32 "
        "{%0,%1,%2,%3}, {%4,%5,%6,%7}, {%8,%9}, {%0,%1,%2,%3};"
        : "+f"(c[0]), "+f"(c[1]), "+f"(c[2]), "+f"(c[3])
        : "r"(a[0]), "r"(a[1]), "r"(a[2]), "r"(a[3]), "r"(b0), "r"(b1));
}
__device__ __forceinline__ void ldsm4(uint32_t r[4], uint32_t addr) {
    asm volatile("ldmatrix.sync.aligned.m8n8.x4.shared.b16 {%0,%1,%2,%3}, [%4];"
                 : "=r"(r[0]), "=r"(r[1]), "=r"(r[2]), "=r"(r[3]) : "r"(addr));
}
__device__ __forceinline__ uint32_t smem_u32(const void* p) {
    return (uint32_t)__cvta_generic_to_shared(p);
}
__device__ __forceinline__ void cp_async16(uint32_t dst, const void* src) {
    asm volatile("cp.async.cg.shared.global [%0], [%1], 16;" :: "r"(dst), "l"(src));
}
#define CP_COMMIT() asm volatile("cp.async.commit_group;" ::: "memory")
#define CP_WAIT(n)  asm volatile("cp.async.wait_group %0;" :: "n"(n) : "memory")

// A tile layout: [rows][128 fp16 = 256B], 16B-granule XOR swizzle:
// phys_byte = row*256 + (((k>>3) ^ (row&7))<<4) + (k&7)*2.

// Stage one granule (8 consecutive k) of x: 2 float4 -> 8 fp16 (one 16B store).
__device__ __forceinline__ void x_store8(char* a, int row, int k8, float4 v0, float4 v1) {
    uint32_t off = (uint32_t)(row * 256 + ((k8 ^ (row & 7)) << 4));
    __half2 h[4];
    h[0] = __floats2half2_rn(v0.x, v0.y);
    h[1] = __floats2half2_rn(v0.z, v0.w);
    h[2] = __floats2half2_rn(v1.x, v1.y);
    h[3] = __floats2half2_rn(v1.z, v1.w);
    *(uint4*)(a + off) = *(const uint4*)h;
}

// Issue both 16KB W chunks of one W tile (two commit groups).
__device__ __forceinline__ void issue_w2(const __half* __restrict__ wsrc,
                                         uint32_t wB, int tid) {
    #pragma unroll
    for (int half = 0; half < 2; half++) {
        const char* src = (const char*)wsrc + half * 128;
        uint32_t buf = wB + (uint32_t)half * 16384;
        #pragma unroll
        for (int l = 0; l < 4; l++) {
            int i = tid + l * 256;
            int n = i >> 3, j = i & 7;
            cp_async16(buf + (uint32_t)i * 16, src + n * 256 + j * 16);
        }
        CP_COMMIT();
    }
}

// Compute 4 global ksteps (ks = half*4 + ksl): acc += A @ Wchunk.
__device__ __forceinline__ void gemm_chunk(uint32_t aT, uint32_t wbuf, int half,
                                           float acc[2][4][4], int r0, int c0, int lane) {
    const int l7 = lane & 7;
    const int am8 = ((lane >> 3) & 1) << 3;
    const int akh = lane >> 4;
    const int bm8 = ((lane >> 4) & 1) << 3;
    const int bpar = (lane >> 3) & 1;
    uint32_t arow[2], brow[2];
    int arow7[2], brow7[2];
    #pragma unroll
    for (int mt = 0; mt < 2; mt++) {
        int r = r0 + mt * 16 + am8 + l7;
        arow[mt] = (uint32_t)(r * 256); arow7[mt] = r & 7;
    }
    #pragma unroll
    for (int n2 = 0; n2 < 2; n2++) {
        int r = c0 + n2 * 16 + bm8 + l7;
        brow[n2] = (uint32_t)(r * 128); brow7[n2] = r & 7;
    }
    #pragma unroll
    for (int ksl = 0; ksl < 4; ksl++) {
        int ks = half * 4 + ksl;
        uint32_t Af[2][4], Bf[2][4];
        #pragma unroll
        for (int mt = 0; mt < 2; mt++) {
            uint32_t g = (uint32_t)(((2 * ks + akh) ^ arow7[mt]) << 4);
            ldsm4(Af[mt], aT + arow[mt] + g);
        }
        #pragma unroll
        for (int n2 = 0; n2 < 2; n2++) {
            uint32_t g = (uint32_t)(((2 * ksl + bpar) ^ brow7[n2]) << 4);
            ldsm4(Bf[n2], wbuf + brow[n2] + g);
        }
        #pragma unroll
        for (int n2 = 0; n2 < 2; n2++)
            #pragma unroll
            for (int j = 0; j < 2; j++) {
                int nt = n2 * 2 + j;
                uint32_t b0 = Bf[n2][j * 2], b1 = Bf[n2][j * 2 + 1];
                #pragma unroll
                for (int mt = 0; mt < 2; mt++)
                    mma16816(acc[mt][nt], Af[mt], b0, b1);
            }
    }
}

// Full GEMM from pre-issued chunks: waits chunk-by-chunk, computes.
__device__ __forceinline__ void gemm_go(uint32_t aT, uint32_t wB, float acc[2][4][4],
                                        int r0, int c0, int lane) {
    #pragma unroll
    for (int mt = 0; mt < 2; mt++)
        #pragma unroll
        for (int nt = 0; nt < 4; nt++)
            #pragma unroll
            for (int i = 0; i < 4; i++) acc[mt][nt][i] = 0.f;
    CP_WAIT(1);
    __syncthreads();
    gemm_chunk(aT, wB, 0, acc, r0, c0, lane);
    CP_WAIT(0);
    __syncthreads();
    gemm_chunk(aT, wB + 16384, 1, acc, r0, c0, lane);
}

// bias + RoPE + elu+1 on accumulators.
__device__ __forceinline__ void rope_elu_acc(float acc[2][4][4],
                                             const float* bias_s, int c0, int tg,
                                             const float sn[4][2], const float cs[4][2]) {
    #pragma unroll
    for (int mt = 0; mt < 2; mt++)
        #pragma unroll
        for (int t = 0; t < 2; t++)
            #pragma unroll
            for (int i = 0; i < 4; i++) {
                int ridx = mt * 2 + (i >> 1);
                int jj = i & 1;
                float x1 = acc[mt][2 * t][i]     + bias_s[c0 + t * 16 + tg * 2 + jj];
                float x2 = acc[mt][2 * t + 1][i] + bias_s[c0 + t * 16 + 8 + tg * 2 + jj];
                float s = sn[ridx][jj], c = cs[ridx][jj];
                float y1 = x1 * c - x2 * s;
                float y2 = x1 * s + x2 * c;
                acc[mt][2 * t][i]     = y1 > 0.f ? y1 + 1.f : __expf(y1);
                acc[mt][2 * t + 1][i] = y2 > 0.f ? y2 + 1.f : __expf(y2);
            }
}

// Store accumulators as fp16 tile [rows][128 fp16], 16B-granule swizzle.
__device__ __forceinline__ void acc_storeH(char* dstH, const float acc[2][4][4],
                                           int r0, int c0, int qid, int tg) {
    #pragma unroll
    for (int mt = 0; mt < 2; mt++)
        #pragma unroll
        for (int nt = 0; nt < 4; nt++)
            #pragma unroll
            for (int h2 = 0; h2 < 2; h2++) {
                int row = r0 + mt * 16 + h2 * 8 + qid;
                int col = c0 + nt * 8 + tg * 2;
                uint32_t off = (uint32_t)(row * 256 +
                    (((col >> 3) ^ (row & 7)) << 4) + (col & 7) * 2);
                *(__half2*)(dstH + off) =
                    __floats2half2_rn(acc[mt][nt][h2 * 2], acc[mt][nt][h2 * 2 + 1]);
            }
}

// Store accumulators TRANSPOSED as fp16: dstT[feature][t], rows 128B,
// phys = f*128 + (((t>>3) ^ (f&7))<<4) + (t&7)*2.
__device__ __forceinline__ void acc_storeT(char* dstT, const float acc[2][4][4],
                                           const float* bias_s, bool add_bias,
                                           int r0, int c0, int qid, int tg) {
    #pragma unroll
    for (int mt = 0; mt < 2; mt++)
        #pragma unroll
        for (int nt = 0; nt < 4; nt++)
            #pragma unroll
            for (int i = 0; i < 4; i++) {
                int t = r0 + mt * 16 + (i >> 1) * 8 + qid;
                int f = c0 + nt * 8 + tg * 2 + (i & 1);
                float v = acc[mt][nt][i];
                if (add_bias) v += bias_s[f];
                uint32_t off = (uint32_t)(f * 128 + (((t >> 3) ^ (f & 7)) << 4) + (t & 7) * 2);
                *(__half*)(dstT + off) = __float2half_rn(v);
            }
}

// Load rope tables from global.
__device__ __forceinline__ void load_rope(int t0, int r0, int qid, int tg,
                                          float sn[4][2], float cs[4][2]) {
    #pragma unroll
    for (int ridx = 0; ridx < 4; ridx++) {
        int mt = ridx >> 1, half = ridx & 1;
        int t = t0 + r0 + mt * 16 + half * 8 + qid;
        float4 v = *(const float4*)&g_rope[t * 16 + tg * 4];
        sn[ridx][0] = v.x; cs[ridx][0] = v.y;
        sn[ridx][1] = v.z; cs[ridx][1] = v.w;
    }
}

// ---------------------------------------------------------------------------
// Kernel 0: setup. Blocks 0-3: W->fp16 swizzled; blocks 4-35: rope tables.
// ---------------------------------------------------------------------------
extern "C" __global__ void __launch_bounds__(256)
la_setup(const float* __restrict__ Wq, const float* __restrict__ Wk,
         const float* __restrict__ Wv, const float* __restrict__ Wo)
{
    if (blockIdx.x < 4) {
        const float* W = (blockIdx.x == 0) ? Wk : (blockIdx.x == 1) ? Wq
                       : (blockIdx.x == 2) ? Wv : Wo;
        __half* wh = g_wt[blockIdx.x];
        const float4* Wp = (const float4*)W;
        for (int i = threadIdx.x; i < 4096; i += 256) {
            int k = i >> 5, n4 = i & 31;
            float4 w = Wp[i];
            float vv[4] = {w.x, w.y, w.z, w.w};
            #pragma unroll
            for (int u = 0; u < 4; u++) {
                int n = n4 * 4 + u;
                uint32_t e = (uint32_t)(n * 128 + ((((k >> 3) ^ (n & 7)) << 3) | (k & 7)));
                wh[e] = __float2half_rn(vv[u]);
            }
        }
    } else {
        const float invf[8] = {1.0f, 0.31622776601683794f, 0.1f, 0.03162277660168379f,
                               0.01f, 0.0031622776601683794f, 0.001f, 0.00031622776601683794f};
        int t = (blockIdx.x - 4) * 256 + threadIdx.x;     // 32 blocks x 256 = 8192
        float tf = (float)t;
        #pragma unroll
        for (int j = 0; j < 8; j++) {
            float s, c;
            sincosf(tf * invf[j], &s, &c);
            g_rope[t * 16 + j * 2] = s;
            g_rope[t * 16 + j * 2 + 1] = c;
        }
    }
}

// ---------------------------------------------------------------------------
// Kernel 1: K, V GEMMs; transposed fp16 k/v tiles; ctx via diagonal MMA.
// smem: A/vT 16K | Wbuf 32K | kT 16K | bias 1K  (~65.5K -> 3 blocks/SM)
// ---------------------------------------------------------------------------
#define KV_WB    16384
#define KV_KT    49152
#define KV_BIAS  65536
#define KV_SMEM  66560

extern "C" __global__ void __launch_bounds__(256, 3)
la_kv(const float* __restrict__ x,
      const float* __restrict__ bk, const float* __restrict__ bv)
{
    extern __shared__ char sm[];
    char* A_t = sm;
    char* kT  = sm + KV_KT;
    char* vT  = sm;                         // alias A (A dead after V GEMM)
    float* bias_s = (float*)(sm + KV_BIAS); // [2][128]: k, v

    const int tid = threadIdx.x;
    const int lane = tid & 31;
    const int wid = tid >> 5;
    const int qid = lane >> 2, tg = lane & 3;
    const int r0 = (wid & 1) * 32;
    const int c0 = (wid >> 1) * 32;
    const int b  = blockIdx.y;
    const int t0 = blockIdx.x * TILE;

    const uint32_t aT  = smem_u32(A_t);
    const uint32_t wB  = smem_u32(sm + KV_WB);
    const uint32_t kTa = smem_u32(kT);
    const uint32_t vTa = aT;

    issue_w2(g_wt[0], wB, tid);             // Wk in flight under x load

    const float4* xp = (const float4*)(x + ((size_t)(b * NT + t0)) * ND);
    for (int i = tid; i < 1024; i += 256) {
        int row = i >> 4, k8 = i & 15;
        x_store8(A_t, row, k8, xp[row * 32 + k8 * 2], xp[row * 32 + k8 * 2 + 1]);
    }
    if (tid < 128) {
        bias_s[tid]       = bk[tid];
        bias_s[128 + tid] = bv[tid];
    }
    float sn[4][2], cs[4][2];
    load_rope(t0, r0, qid, tg, sn, cs);

    float acc[2][4][4];

    // ---- K GEMM (first sync inside gemm_go also publishes A stores) ----
    gemm_go(aT, wB, acc, r0, c0, lane);
    __syncthreads();                        // all Wbuf reads done
    issue_w2(g_wt[2], wB, tid);             // Wv in flight under K epilogue
    rope_elu_acc(acc, bias_s, c0, tg, sn, cs);

    // ksum partials via register shuffles (rows r0..r0+31 per warp)
    {
        float s[8];
        #pragma unroll
        for (int nt = 0; nt < 4; nt++)
            #pragma unroll
            for (int j = 0; j < 2; j++) {
                float v = 0.f;
                #pragma unroll
                for (int mt = 0; mt < 2; mt++)
                    #pragma unroll
                    for (int h2 = 0; h2 < 2; h2++)
                        v += acc[mt][nt][h2 * 2 + j];
                s[nt * 2 + j] = v;
            }
        #pragma unroll
        for (int off = 4; off <= 16; off <<= 1)
            #pragma unroll
            for (int u = 0; u < 8; u++)
                s[u] += __shfl_xor_sync(0xffffffffu, s[u], off);
        if (qid == 0) {
            size_t slot = ((size_t)(b * NTILES + blockIdx.x) * NGRP + (wid & 1));
            #pragma unroll
            for (int nt = 0; nt < 4; nt++)
                #pragma unroll
                for (int j = 0; j < 2; j++)
                    g_partk[slot * 128 + c0 + nt * 8 + tg * 2 + j] = s[nt * 2 + j];
        }
    }
    acc_storeT(kT, acc, bias_s, false, r0, c0, qid, tg);

    // ---- V GEMM ----
    gemm_go(aT, wB, acc, r0, c0, lane);
    __syncthreads();                        // all A reads done before vT overwrite
    acc_storeT(vT, acc, bias_s + 128, true, r0, c0, qid, tg);
    __syncthreads();                        // kT + vT visible

    // ---- ctx via diagonal MMA: warp = (tile = wid&3, tgrp = wid>>2) ----
    {
        const int tile = wid & 3, tgrp = wid >> 2;
        const int base = tile * 32;
        const int l7 = lane & 7;
        const int am8 = ((lane >> 3) & 1) << 3;
        const int akh = lane >> 4;
        const int bm8 = ((lane >> 4) & 1) << 3;
        const int bpar = (lane >> 3) & 1;
        float c2[2][4][4];
        #pragma unroll
        for (int mt = 0; mt < 2; mt++)
            #pragma unroll
            for (int nt = 0; nt < 4; nt++)
                #pragma unroll
                for (int i = 0; i < 4; i++) c2[mt][nt][i] = 0.f;

        #pragma unroll
        for (int ksl = 0; ksl < 2; ksl++) {
            uint32_t Af[2][4], Bf[2][4];
            #pragma unroll
            for (int mt = 0; mt < 2; mt++) {
                int r = base + mt * 16 + am8 + l7;
                uint32_t g = (uint32_t)(((tgrp * 4 + 2 * ksl + akh) ^ (r & 7)) << 4);
                ldsm4(Af[mt], kTa + (uint32_t)(r * 128) + g);
            }
            #pragma unroll
            for (int n2 = 0; n2 < 2; n2++) {
                int r = base + n2 * 16 + bm8 + l7;
                uint32_t g = (uint32_t)(((tgrp * 4 + 2 * ksl + bpar) ^ (r & 7)) << 4);
                ldsm4(Bf[n2], vTa + (uint32_t)(r * 128) + g);
            }
            #pragma unroll
            for (int n2 = 0; n2 < 2; n2++)
                #pragma unroll
                for (int j = 0; j < 2; j++) {
                    int nt = n2 * 2 + j;
                    uint32_t b0 = Bf[n2][j * 2], b1 = Bf[n2][j * 2 + 1];
                    #pragma unroll
                    for (int mt = 0; mt < 2; mt++)
                        mma16816(c2[mt][nt], Af[mt], b0, b1);
                }
        }

        // keep diagonal blocks: mt == nt>>1
        size_t slot = ((size_t)(b * NTILES + blockIdx.x) * NGRP + tgrp);
        float* pp = g_part + slot * 2048;
        #pragma unroll
        for (int mt = 0; mt < 2; mt++)
            #pragma unroll
            for (int n1 = 0; n1 < 2; n1++) {
                int nt = mt * 2 + n1;
                #pragma unroll
                for (int i = 0; i < 4; i++) {
                    int head = tile * 2 + mt;
                    int d = (i >> 1) * 8 + qid;
                    int e = n1 * 8 + tg * 2 + (i & 1);
                    pp[head * 256 + d * 16 + e] = c2[mt][nt][i];
                }
            }
    }
}

// ---------------------------------------------------------------------------
// Kernel 2: reduce partials; build block-diagonal ctx tile (fp16, W layout).
// grid = NB*8 blocks (block ch owns head ch of batch b), 256 threads.
// ---------------------------------------------------------------------------
extern "C" __global__ void __launch_bounds__(256)
la_red()
{
    int b = blockIdx.x >> 3, ch = blockIdx.x & 7;
    int e = ch * 256 + threadIdx.x;
    const float* pc = g_part + (size_t)b * NTILES * NGRP * 2048;
    float s0 = 0.f, s1 = 0.f, s2 = 0.f, s3 = 0.f;
    for (int j = 0; j < NTILES * NGRP; j += 4) {
        s0 += pc[(size_t)j * 2048 + e];
        s1 += pc[(size_t)(j + 1) * 2048 + e];
        s2 += pc[(size_t)(j + 2) * 2048 + e];
        s3 += pc[(size_t)(j + 3) * 2048 + e];
    }
    float s = (s0 + s1) + (s2 + s3);

    // zero this head's 16 rows of ctxBD (rows n in [ch*16, ch*16+16), 256B each)
    __half* bd = g_ctxBD[b];
    ((uint4*)(bd + ch * 16 * 128))[threadIdx.x] = make_uint4(0, 0, 0, 0);
    __syncthreads();

    // scatter diagonal entry: ctx[h=ch][d][e2] -> B[n = ch*16+e2][k = ch*16+d]
    {
        int d  = threadIdx.x >> 4;
        int e2 = threadIdx.x & 15;
        int n  = ch * 16 + e2;
        int kg = ch * 16 + d;
        bd[n * 128 + ((((kg >> 3) ^ (n & 7)) << 3) | (kg & 7))] = __float2half_rn(s);
    }

    if (ch == 0 && threadIdx.x < 128) {
        const float* pk = g_partk + (size_t)b * NTILES * NGRP * 128;
        float k0 = 0.f, k1 = 0.f, k2 = 0.f, k3 = 0.f;
        for (int j = 0; j < NTILES * NGRP; j += 4) {
            k0 += pk[(size_t)j * 128 + threadIdx.x];
            k1 += pk[(size_t)(j + 1) * 128 + threadIdx.x];
            k2 += pk[(size_t)(j + 2) * 128 + threadIdx.x];
            k3 += pk[(size_t)(j + 3) * 128 + threadIdx.x];
        }
        g_ksum[b * 128 + threadIdx.x] = (k0 + k1) + (k2 + k3);
    }
}

// ---------------------------------------------------------------------------
// Kernel 3: q = rope_elu(x@Wq+bq); attn = (q@ctxBD)*z (MMA); out = attn@Wo+bo.
// smem: A 16K | Wbuf 32K | z 2.3K | ksum .5K | bias 1K  (~52K -> 3 blocks/SM)
// ---------------------------------------------------------------------------
#define QO_WB    16384
#define QO_Z     49152
#define QO_KSUM  51456
#define QO_BIAS  51968
#define QO_SMEM  52992

extern "C" __global__ void __launch_bounds__(256, 3)
la_qout(const float* __restrict__ x,
        const float* __restrict__ bq, const float* __restrict__ bo,
        float* __restrict__ out)
{
    extern __shared__ char sm[];
    char* A_t  = sm;
    char* Wbuf = sm + QO_WB;
    float* z_s    = (float*)(sm + QO_Z);     // [64][9] padded
    float* ksum_s = (float*)(sm + QO_KSUM);
    float* bias_s = (float*)(sm + QO_BIAS);  // [2][128]: q, o

    const int tid = threadIdx.x;
    const int lane = tid & 31;
    const int wid = tid >> 5;
    const int qid = lane >> 2, tg = lane & 3;
    const int r0 = (wid & 1) * 32;
    const int c0 = (wid >> 1) * 32;
    const int hA = c0 >> 4;                  // first head of this warp's columns
    const int b  = blockIdx.y;
    const int t0 = blockIdx.x * TILE;

    const uint32_t aT = smem_u32(A_t);
    const uint32_t wB = smem_u32(Wbuf);

    issue_w2(g_wt[1], wB, tid);             // Wq in flight under x load

    const float4* xp = (const float4*)(x + ((size_t)(b * NT + t0)) * ND);
    for (int i = tid; i < 1024; i += 256) {
        int row = i >> 4, k8 = i & 15;
        x_store8(A_t, row, k8, xp[row * 32 + k8 * 2], xp[row * 32 + k8 * 2 + 1]);
    }
    if (tid < 128) {
        ksum_s[tid] = g_ksum[b * 128 + tid];
        bias_s[tid] = bq[tid];
        bias_s[128 + tid] = bo[tid];
    }
    float sn[4][2], cs[4][2];
    load_rope(t0, r0, qid, tg, sn, cs);

    float acc[2][4][4];

    // ---- Q GEMM ----
    gemm_go(aT, wB, acc, r0, c0, lane);
    __syncthreads();                        // Wbuf + A reads done
    issue_w2(g_ctxBD[b], wB, tid);          // ctxBD in flight under epilogue
    rope_elu_acc(acc, bias_s, c0, tg, sn, cs);

    // ---- z = q . ksum (from accumulators, shuffle-reduced over tg lanes) ----
    {
        float zp[2][2][2];                   // [mt][h2][g]
        #pragma unroll
        for (int mt = 0; mt < 2; mt++)
            #pragma unroll
            for (int h2 = 0; h2 < 2; h2++)
                #pragma unroll
                for (int g = 0; g < 2; g++) {
                    float s = 0.f;
                    #pragma unroll
                    for (int n1 = 0; n1 < 2; n1++) {
                        int nt = g * 2 + n1;
                        #pragma unroll
                        for (int j = 0; j < 2; j++)
                            s = fmaf(acc[mt][nt][h2 * 2 + j],
                                     ksum_s[c0 + nt * 8 + tg * 2 + j], s);
                    }
                    zp[mt][h2][g] = s;
                }
        #pragma unroll
        for (int off = 1; off <= 2; off <<= 1)
            #pragma unroll
            for (int mt = 0; mt < 2; mt++)
                #pragma unroll
                for (int h2 = 0; h2 < 2; h2++)
                    #pragma unroll
                    for (int g = 0; g < 2; g++)
                        zp[mt][h2][g] += __shfl_xor_sync(0xffffffffu, zp[mt][h2][g], off);
        if (tg == 0) {
            #pragma unroll
            for (int mt = 0; mt < 2; mt++)
                #pragma unroll
                for (int h2 = 0; h2 < 2; h2++) {
                    int row = r0 + mt * 16 + h2 * 8 + qid;
                    #pragma unroll
                    for (int g = 0; g < 2; g++)
                        z_s[row * 9 + hA + g] = zp[mt][h2][g] + 1e-6f;
                }
        }
    }

    // ---- store q into A tile (x dead) ----
    acc_storeH(A_t, acc, r0, c0, qid, tg);

    // ---- apply GEMM: attn = q @ ctxBD (syncs publish q stores + z_s) ----
    gemm_go(aT, wB, acc, r0, c0, lane);
    __syncthreads();                        // Wbuf + A reads done

    issue_w2(g_wt[3], wB, tid);             // Wo in flight under scale+store

    // ---- z-scale and store attn into A tile ----
    {
        float zi[2][2][2];
        #pragma unroll
        for (int mt = 0; mt < 2; mt++)
            #pragma unroll
            for (int h2 = 0; h2 < 2; h2++) {
                int row = r0 + mt * 16 + h2 * 8 + qid;
                #pragma unroll
                for (int g = 0; g < 2; g++)
                    zi[mt][h2][g] = 1.f / z_s[row * 9 + hA + g];
            }
        #pragma unroll
        for (int mt = 0; mt < 2; mt++)
            #pragma unroll
            for (int nt = 0; nt < 4; nt++) {
                int g = nt >> 1;
                #pragma unroll
                for (int h2 = 0; h2 < 2; h2++) {
                    acc[mt][nt][h2 * 2]     *= zi[mt][h2][g];
                    acc[mt][nt][h2 * 2 + 1] *= zi[mt][h2][g];
                }
            }
        acc_storeH(A_t, acc, r0, c0, qid, tg);
    }

    // ---- O GEMM (first sync inside gemm_go publishes attn stores) ----
    gemm_go(aT, wB, acc, r0, c0, lane);

    // direct global store with bias
    {
        float* op = out + ((size_t)(b * NT + t0)) * ND;
        #pragma unroll
        for (int mt = 0; mt < 2; mt++)
            #pragma unroll
            for (int nt = 0; nt < 4; nt++)
                #pragma unroll
                for (int h2 = 0; h2 < 2; h2++) {
                    int row = r0 + mt * 16 + h2 * 8 + qid;
                    int col = c0 + nt * 8 + tg * 2;
                    *(float2*)(op + (size_t)row * ND + col) =
                        make_float2(acc[mt][nt][h2 * 2] + bias_s[128 + col],
                                    acc[mt][nt][h2 * 2 + 1] + bias_s[128 + col + 1]);
                }
    }
}

// ---------------------------------------------------------------------------
extern "C" void kernel_launch(void* const* d_in, const int* in_sizes, int n_in,
                              void* d_out, int out_size)
{
    const float* x  = (const float*)d_in[0];
    const float* Wq = (const float*)d_in[1];
    const float* bq = (const float*)d_in[2];
    const float* Wk = (const float*)d_in[3];
    const float* bk = (const float*)d_in[4];
    const float* Wv = (const float*)d_in[5];
    const float* bv = (const float*)d_in[6];
    const float* Wo = (const float*)d_in[7];
    const float* bo = (const float*)d_in[8];
    float* out = (float*)d_out;

    cudaFuncSetAttribute(la_kv,   cudaFuncAttributeMaxDynamicSharedMemorySize, KV_SMEM);
    cudaFuncSetAttribute(la_qout, cudaFuncAttributeMaxDynamicSharedMemorySize, QO_SMEM);

    la_setup<<<36, 256>>>(Wq, Wk, Wv, Wo);

    dim3 grid(NT / TILE, NB);
    la_kv<<<grid, 256, KV_SMEM>>>(x, bk, bv);
    la_red<<<NB * 8, 256>>>();
    la_qout<<<grid, 256, QO_SMEM>>>(x, bq, bo, out);
}

// round 16
// speedup vs baseline: 1.0707x; 1.0288x over previous
#include <cuda_runtime.h>
#include <cuda_fp16.h>
#include <math.h>
#include <stdint.h>

#define NB 8
#define NT 8192
#define ND 128
#define NH 8
#define TILE 64
#define NTILES 128             // NT / TILE
#define NGRP 2                 // partial groups per block
#define ZSCALE 1024.0f         // q·z pre-scale (cancelled by M/1024)

// ---------------- scratch (device globals; no allocs allowed) ---------------
static __device__ float g_part[NB * NTILES * NGRP * 2048];  // ctx partials
static __device__ float g_partk[NB * NTILES * NGRP * 128];  // ksum partials
static __device__ float g_ksum[NB * 128];                   // [b][h*16+d]
static __device__ __half g_wt[4][16384];                    // W tiles (fp16, swizzled)
static __device__ __half g_mb[NB][16384];                   // M = ctxBD@Wo / 1024 (fp16)
static __device__ float g_rope[NT * 16];                    // [t][j*2]=sin, [j*2+1]=cos

// ---------------------------------------------------------------------------
__device__ __forceinline__ void mma16816(float c[4], const uint32_t a[4],
                                         uint32_t b0, uint32_t b1) {
    asm volatile(
        "mma.sync.aligned.m16n8k16.row.col.f32.f16.f16.f32 "
        "{%0,%1,%2,%3}, {%4,%5,%6,%7}, {%8,%9}, {%0,%1,%2,%3};"
        : "+f"(c[0]), "+f"(c[1]), "+f"(c[2]), "+f"(c[3])
        : "r"(a[0]), "r"(a[1]), "r"(a[2]), "r"(a[3]), "r"(b0), "r"(b1));
}
__device__ __forceinline__ void ldsm4(uint32_t r[4], uint32_t addr) {
    asm volatile("ldmatrix.sync.aligned.m8n8.x4.shared.b16 {%0,%1,%2,%3}, [%4];"
                 : "=r"(r[0]), "=r"(r[1]), "=r"(r[2]), "=r"(r[3]) : "r"(addr));
}
__device__ __forceinline__ uint32_t smem_u32(const void* p) {
    return (uint32_t)__cvta_generic_to_shared(p);
}
__device__ __forceinline__ void cp_async16(uint32_t dst, const void* src) {
    asm volatile("cp.async.cg.shared.global [%0], [%1], 16;" :: "r"(dst), "l"(src));
}
#define CP_COMMIT() asm volatile("cp.async.commit_group;" ::: "memory")
#define CP_WAIT(n)  asm volatile("cp.async.wait_group %0;" :: "n"(n) : "memory")

// A tile layout: [rows][128 fp16 = 256B], 16B-granule XOR swizzle:
// phys_byte = row*256 + (((k>>3) ^ (row&7))<<4) + (k&7)*2.

// Stage one granule (8 consecutive k) of x: 2 float4 -> 8 fp16 (one 16B store).
__device__ __forceinline__ void x_store8(char* a, int row, int k8, float4 v0, float4 v1) {
    uint32_t off = (uint32_t)(row * 256 + ((k8 ^ (row & 7)) << 4));
    __half2 h[4];
    h[0] = __floats2half2_rn(v0.x, v0.y);
    h[1] = __floats2half2_rn(v0.z, v0.w);
    h[2] = __floats2half2_rn(v1.x, v1.y);
    h[3] = __floats2half2_rn(v1.z, v1.w);
    *(uint4*)(a + off) = *(const uint4*)h;
}

// Issue both 16KB W chunks of one W tile (two commit groups).
__device__ __forceinline__ void issue_w2(const __half* __restrict__ wsrc,
                                         uint32_t wB, int tid) {
    #pragma unroll
    for (int half = 0; half < 2; half++) {
        const char* src = (const char*)wsrc + half * 128;
        uint32_t buf = wB + (uint32_t)half * 16384;
        #pragma unroll
        for (int l = 0; l < 4; l++) {
            int i = tid + l * 256;
            int n = i >> 3, j = i & 7;
            cp_async16(buf + (uint32_t)i * 16, src + n * 256 + j * 16);
        }
        CP_COMMIT();
    }
}

// Compute 4 global ksteps (ks = half*4 + ksl): acc += A @ Wchunk.
__device__ __forceinline__ void gemm_chunk(uint32_t aT, uint32_t wbuf, int half,
                                           float acc[2][4][4], int r0, int c0, int lane) {
    const int l7 = lane & 7;
    const int am8 = ((lane >> 3) & 1) << 3;
    const int akh = lane >> 4;
    const int bm8 = ((lane >> 4) & 1) << 3;
    const int bpar = (lane >> 3) & 1;
    uint32_t arow[2], brow[2];
    int arow7[2], brow7[2];
    #pragma unroll
    for (int mt = 0; mt < 2; mt++) {
        int r = r0 + mt * 16 + am8 + l7;
        arow[mt] = (uint32_t)(r * 256); arow7[mt] = r & 7;
    }
    #pragma unroll
    for (int n2 = 0; n2 < 2; n2++) {
        int r = c0 + n2 * 16 + bm8 + l7;
        brow[n2] = (uint32_t)(r * 128); brow7[n2] = r & 7;
    }
    #pragma unroll
    for (int ksl = 0; ksl < 4; ksl++) {
        int ks = half * 4 + ksl;
        uint32_t Af[2][4], Bf[2][4];
        #pragma unroll
        for (int mt = 0; mt < 2; mt++) {
            uint32_t g = (uint32_t)(((2 * ks + akh) ^ arow7[mt]) << 4);
            ldsm4(Af[mt], aT + arow[mt] + g);
        }
        #pragma unroll
        for (int n2 = 0; n2 < 2; n2++) {
            uint32_t g = (uint32_t)(((2 * ksl + bpar) ^ brow7[n2]) << 4);
            ldsm4(Bf[n2], wbuf + brow[n2] + g);
        }
        #pragma unroll
        for (int n2 = 0; n2 < 2; n2++)
            #pragma unroll
            for (int j = 0; j < 2; j++) {
                int nt = n2 * 2 + j;
                uint32_t b0 = Bf[n2][j * 2], b1 = Bf[n2][j * 2 + 1];
                #pragma unroll
                for (int mt = 0; mt < 2; mt++)
                    mma16816(acc[mt][nt], Af[mt], b0, b1);
            }
    }
}

// Full GEMM from pre-issued chunks: waits chunk-by-chunk, computes.
__device__ __forceinline__ void gemm_go(uint32_t aT, uint32_t wB, float acc[2][4][4],
                                        int r0, int c0, int lane) {
    #pragma unroll
    for (int mt = 0; mt < 2; mt++)
        #pragma unroll
        for (int nt = 0; nt < 4; nt++)
            #pragma unroll
            for (int i = 0; i < 4; i++) acc[mt][nt][i] = 0.f;
    CP_WAIT(1);
    __syncthreads();
    gemm_chunk(aT, wB, 0, acc, r0, c0, lane);
    CP_WAIT(0);
    __syncthreads();
    gemm_chunk(aT, wB + 16384, 1, acc, r0, c0, lane);
}

// bias + RoPE + elu+1 on accumulators.
__device__ __forceinline__ void rope_elu_acc(float acc[2][4][4],
                                             const float* bias_s, int c0, int tg,
                                             const float sn[4][2], const float cs[4][2]) {
    #pragma unroll
    for (int mt = 0; mt < 2; mt++)
        #pragma unroll
        for (int t = 0; t < 2; t++)
            #pragma unroll
            for (int i = 0; i < 4; i++) {
                int ridx = mt * 2 + (i >> 1);
                int jj = i & 1;
                float x1 = acc[mt][2 * t][i]     + bias_s[c0 + t * 16 + tg * 2 + jj];
                float x2 = acc[mt][2 * t + 1][i] + bias_s[c0 + t * 16 + 8 + tg * 2 + jj];
                float s = sn[ridx][jj], c = cs[ridx][jj];
                float y1 = x1 * c - x2 * s;
                float y2 = x1 * s + x2 * c;
                acc[mt][2 * t][i]     = y1 > 0.f ? y1 + 1.f : __expf(y1);
                acc[mt][2 * t + 1][i] = y2 > 0.f ? y2 + 1.f : __expf(y2);
            }
}

// Store accumulators as fp16 tile [rows][128 fp16], 16B-granule swizzle.
__device__ __forceinline__ void acc_storeH(char* dstH, const float acc[2][4][4],
                                           int r0, int c0, int qid, int tg) {
    #pragma unroll
    for (int mt = 0; mt < 2; mt++)
        #pragma unroll
        for (int nt = 0; nt < 4; nt++)
            #pragma unroll
            for (int h2 = 0; h2 < 2; h2++) {
                int row = r0 + mt * 16 + h2 * 8 + qid;
                int col = c0 + nt * 8 + tg * 2;
                uint32_t off = (uint32_t)(row * 256 +
                    (((col >> 3) ^ (row & 7)) << 4) + (col & 7) * 2);
                *(__half2*)(dstH + off) =
                    __floats2half2_rn(acc[mt][nt][h2 * 2], acc[mt][nt][h2 * 2 + 1]);
            }
}

// Store accumulators TRANSPOSED as fp16: dstT[feature][t], rows 128B,
// phys = f*128 + (((t>>3) ^ (f&7))<<4) + (t&7)*2.
__device__ __forceinline__ void acc_storeT(char* dstT, const float acc[2][4][4],
                                           const float* bias_s, bool add_bias,
                                           int r0, int c0, int qid, int tg) {
    #pragma unroll
    for (int mt = 0; mt < 2; mt++)
        #pragma unroll
        for (int nt = 0; nt < 4; nt++)
            #pragma unroll
            for (int i = 0; i < 4; i++) {
                int t = r0 + mt * 16 + (i >> 1) * 8 + qid;
                int f = c0 + nt * 8 + tg * 2 + (i & 1);
                float v = acc[mt][nt][i];
                if (add_bias) v += bias_s[f];
                uint32_t off = (uint32_t)(f * 128 + (((t >> 3) ^ (f & 7)) << 4) + (t & 7) * 2);
                *(__half*)(dstT + off) = __float2half_rn(v);
            }
}

// Load rope tables from global.
__device__ __forceinline__ void load_rope(int t0, int r0, int qid, int tg,
                                          float sn[4][2], float cs[4][2]) {
    #pragma unroll
    for (int ridx = 0; ridx < 4; ridx++) {
        int mt = ridx >> 1, half = ridx & 1;
        int t = t0 + r0 + mt * 16 + half * 8 + qid;
        float4 v = *(const float4*)&g_rope[t * 16 + tg * 4];
        sn[ridx][0] = v.x; cs[ridx][0] = v.y;
        sn[ridx][1] = v.z; cs[ridx][1] = v.w;
    }
}

// ---------------------------------------------------------------------------
// Kernel 0: setup. Blocks 0-3: W->fp16 swizzled; blocks 4-35: rope tables.
// ---------------------------------------------------------------------------
extern "C" __global__ void __launch_bounds__(256)
la_setup(const float* __restrict__ Wq, const float* __restrict__ Wk,
         const float* __restrict__ Wv, const float* __restrict__ Wo)
{
    if (blockIdx.x < 4) {
        const float* W = (blockIdx.x == 0) ? Wk : (blockIdx.x == 1) ? Wq
                       : (blockIdx.x == 2) ? Wv : Wo;
        __half* wh = g_wt[blockIdx.x];
        const float4* Wp = (const float4*)W;
        for (int i = threadIdx.x; i < 4096; i += 256) {
            int k = i >> 5, n4 = i & 31;
            float4 w = Wp[i];
            float vv[4] = {w.x, w.y, w.z, w.w};
            #pragma unroll
            for (int u = 0; u < 4; u++) {
                int n = n4 * 4 + u;
                uint32_t e = (uint32_t)(n * 128 + ((((k >> 3) ^ (n & 7)) << 3) | (k & 7)));
                wh[e] = __float2half_rn(vv[u]);
            }
        }
    } else {
        const float invf[8] = {1.0f, 0.31622776601683794f, 0.1f, 0.03162277660168379f,
                               0.01f, 0.0031622776601683794f, 0.001f, 0.00031622776601683794f};
        int t = (blockIdx.x - 4) * 256 + threadIdx.x;     // 32 blocks x 256 = 8192
        float tf = (float)t;
        #pragma unroll
        for (int j = 0; j < 8; j++) {
            float s, c;
            sincosf(tf * invf[j], &s, &c);
            g_rope[t * 16 + j * 2] = s;
            g_rope[t * 16 + j * 2 + 1] = c;
        }
    }
}

// ---------------------------------------------------------------------------
// Kernel 1: K, V GEMMs; transposed fp16 k/v tiles; ctx via diagonal MMA.
// smem: A/vT 16K | Wbuf 32K | kT 16K | bias 1K  (~65.5K -> 3 blocks/SM)
// ---------------------------------------------------------------------------
#define KV_WB    16384
#define KV_KT    49152
#define KV_BIAS  65536
#define KV_SMEM  66560

extern "C" __global__ void __launch_bounds__(256, 3)
la_kv(const float* __restrict__ x,
      const float* __restrict__ bk, const float* __restrict__ bv)
{
    extern __shared__ char sm[];
    char* A_t = sm;
    char* kT  = sm + KV_KT;
    char* vT  = sm;                         // alias A (A dead after V GEMM)
    float* bias_s = (float*)(sm + KV_BIAS); // [2][128]: k, v

    const int tid = threadIdx.x;
    const int lane = tid & 31;
    const int wid = tid >> 5;
    const int qid = lane >> 2, tg = lane & 3;
    const int r0 = (wid & 1) * 32;
    const int c0 = (wid >> 1) * 32;
    const int b  = blockIdx.y;
    const int t0 = blockIdx.x * TILE;

    const uint32_t aT  = smem_u32(A_t);
    const uint32_t wB  = smem_u32(sm + KV_WB);
    const uint32_t kTa = smem_u32(kT);
    const uint32_t vTa = aT;

    issue_w2(g_wt[0], wB, tid);             // Wk in flight under x load

    const float4* xp = (const float4*)(x + ((size_t)(b * NT + t0)) * ND);
    for (int i = tid; i < 1024; i += 256) {
        int row = i >> 4, k8 = i & 15;
        x_store8(A_t, row, k8, xp[row * 32 + k8 * 2], xp[row * 32 + k8 * 2 + 1]);
    }
    if (tid < 128) {
        bias_s[tid]       = bk[tid];
        bias_s[128 + tid] = bv[tid];
    }
    float sn[4][2], cs[4][2];
    load_rope(t0, r0, qid, tg, sn, cs);

    float acc[2][4][4];

    // ---- K GEMM (first sync inside gemm_go also publishes A stores) ----
    gemm_go(aT, wB, acc, r0, c0, lane);
    __syncthreads();                        // all Wbuf reads done
    issue_w2(g_wt[2], wB, tid);             // Wv in flight under K epilogue
    rope_elu_acc(acc, bias_s, c0, tg, sn, cs);

    // ksum partials via register shuffles (rows r0..r0+31 per warp)
    {
        float s[8];
        #pragma unroll
        for (int nt = 0; nt < 4; nt++)
            #pragma unroll
            for (int j = 0; j < 2; j++) {
                float v = 0.f;
                #pragma unroll
                for (int mt = 0; mt < 2; mt++)
                    #pragma unroll
                    for (int h2 = 0; h2 < 2; h2++)
                        v += acc[mt][nt][h2 * 2 + j];
                s[nt * 2 + j] = v;
            }
        #pragma unroll
        for (int off = 4; off <= 16; off <<= 1)
            #pragma unroll
            for (int u = 0; u < 8; u++)
                s[u] += __shfl_xor_sync(0xffffffffu, s[u], off);
        if (qid == 0) {
            size_t slot = ((size_t)(b * NTILES + blockIdx.x) * NGRP + (wid & 1));
            #pragma unroll
            for (int nt = 0; nt < 4; nt++)
                #pragma unroll
                for (int j = 0; j < 2; j++)
                    g_partk[slot * 128 + c0 + nt * 8 + tg * 2 + j] = s[nt * 2 + j];
        }
    }
    acc_storeT(kT, acc, bias_s, false, r0, c0, qid, tg);

    // ---- V GEMM ----
    gemm_go(aT, wB, acc, r0, c0, lane);
    __syncthreads();                        // all A reads done before vT overwrite
    acc_storeT(vT, acc, bias_s + 128, true, r0, c0, qid, tg);
    __syncthreads();                        // kT + vT visible

    // ---- ctx via diagonal MMA: warp = (tile = wid&3, tgrp = wid>>2) ----
    {
        const int tile = wid & 3, tgrp = wid >> 2;
        const int base = tile * 32;
        const int l7 = lane & 7;
        const int am8 = ((lane >> 3) & 1) << 3;
        const int akh = lane >> 4;
        const int bm8 = ((lane >> 4) & 1) << 3;
        const int bpar = (lane >> 3) & 1;
        float c2[2][4][4];
        #pragma unroll
        for (int mt = 0; mt < 2; mt++)
            #pragma unroll
            for (int nt = 0; nt < 4; nt++)
                #pragma unroll
                for (int i = 0; i < 4; i++) c2[mt][nt][i] = 0.f;

        #pragma unroll
        for (int ksl = 0; ksl < 2; ksl++) {
            uint32_t Af[2][4], Bf[2][4];
            #pragma unroll
            for (int mt = 0; mt < 2; mt++) {
                int r = base + mt * 16 + am8 + l7;
                uint32_t g = (uint32_t)(((tgrp * 4 + 2 * ksl + akh) ^ (r & 7)) << 4);
                ldsm4(Af[mt], kTa + (uint32_t)(r * 128) + g);
            }
            #pragma unroll
            for (int n2 = 0; n2 < 2; n2++) {
                int r = base + n2 * 16 + bm8 + l7;
                uint32_t g = (uint32_t)(((tgrp * 4 + 2 * ksl + bpar) ^ (r & 7)) << 4);
                ldsm4(Bf[n2], vTa + (uint32_t)(r * 128) + g);
            }
            #pragma unroll
            for (int n2 = 0; n2 < 2; n2++)
                #pragma unroll
                for (int j = 0; j < 2; j++) {
                    int nt = n2 * 2 + j;
                    uint32_t b0 = Bf[n2][j * 2], b1 = Bf[n2][j * 2 + 1];
                    #pragma unroll
                    for (int mt = 0; mt < 2; mt++)
                        mma16816(c2[mt][nt], Af[mt], b0, b1);
                }
        }

        // keep diagonal blocks: mt == nt>>1
        size_t slot = ((size_t)(b * NTILES + blockIdx.x) * NGRP + tgrp);
        float* pp = g_part + slot * 2048;
        #pragma unroll
        for (int mt = 0; mt < 2; mt++)
            #pragma unroll
            for (int n1 = 0; n1 < 2; n1++) {
                int nt = mt * 2 + n1;
                #pragma unroll
                for (int i = 0; i < 4; i++) {
                    int head = tile * 2 + mt;
                    int d = (i >> 1) * 8 + qid;
                    int e = n1 * 8 + tg * 2 + (i & 1);
                    pp[head * 256 + d * 16 + e] = c2[mt][nt][i];
                }
            }
    }
}

// ---------------------------------------------------------------------------
// Kernel 2: reduce partials; build M_b = ctxBD @ Wo / ZSCALE (fp16, W layout).
// grid = NB*8 blocks (block ch owns head ch of batch b), 256 threads.
// ---------------------------------------------------------------------------
extern "C" __global__ void __launch_bounds__(256)
la_red(const float* __restrict__ Wo)
{
    __shared__ float ctx_s[16][17];
    int b = blockIdx.x >> 3, ch = blockIdx.x & 7;
    int e = ch * 256 + threadIdx.x;
    const float* pc = g_part + (size_t)b * NTILES * NGRP * 2048;
    float s0 = 0.f, s1 = 0.f, s2 = 0.f, s3 = 0.f;
    for (int j = 0; j < NTILES * NGRP; j += 4) {
        s0 += pc[(size_t)j * 2048 + e];
        s1 += pc[(size_t)(j + 1) * 2048 + e];
        s2 += pc[(size_t)(j + 2) * 2048 + e];
        s3 += pc[(size_t)(j + 3) * 2048 + e];
    }
    float s = (s0 + s1) + (s2 + s3);
    int d = threadIdx.x >> 4, e2 = threadIdx.x & 15;
    ctx_s[d][e2] = s;

    if (ch == 0 && threadIdx.x < 128) {
        const float* pk = g_partk + (size_t)b * NTILES * NGRP * 128;
        float k0 = 0.f, k1 = 0.f, k2 = 0.f, k3 = 0.f;
        for (int j = 0; j < NTILES * NGRP; j += 4) {
            k0 += pk[(size_t)j * 128 + threadIdx.x];
            k1 += pk[(size_t)(j + 1) * 128 + threadIdx.x];
            k2 += pk[(size_t)(j + 2) * 128 + threadIdx.x];
            k3 += pk[(size_t)(j + 3) * 128 + threadIdx.x];
        }
        g_ksum[b * 128 + threadIdx.x] = (k0 + k1) + (k2 + k3);
    }
    __syncthreads();

    // M rows [ch*16, ch*16+16): thread (d2, nc) computes 8 cols.
    {
        int d2 = threadIdx.x >> 4, nc = threadIdx.x & 15;
        __half* mb = g_mb[b];
        int k = ch * 16 + d2;
        #pragma unroll
        for (int j = 0; j < 8; j++) {
            int n = nc * 8 + j;
            float m = 0.f;
            #pragma unroll
            for (int e3 = 0; e3 < 16; e3++)
                m = fmaf(ctx_s[d2][e3], Wo[(ch * 16 + e3) * 128 + n], m);
            mb[n * 128 + ((((k >> 3) ^ (n & 7)) << 3) | (k & 7))] =
                __float2half_rn(m * (1.f / ZSCALE));
        }
    }
}

// ---------------------------------------------------------------------------
// Kernel 3: q = rope_elu(x@Wq+bq); out = (q*z*S) @ (ctxBD@Wo/S) + bo.
// smem: A 16K | Wbuf 32K | ksum .5K | bias 1K  (~50K -> 3 blocks/SM)
// ---------------------------------------------------------------------------
#define QO_WB    16384
#define QO_KSUM  49152
#define QO_BIAS  49664
#define QO_SMEM  50688

extern "C" __global__ void __launch_bounds__(256, 3)
la_qout(const float* __restrict__ x,
        const float* __restrict__ bq, const float* __restrict__ bo,
        float* __restrict__ out)
{
    extern __shared__ char sm[];
    char* A_t  = sm;
    char* Wbuf = sm + QO_WB;
    float* ksum_s = (float*)(sm + QO_KSUM);
    float* bias_s = (float*)(sm + QO_BIAS);  // [2][128]: q, o

    const int tid = threadIdx.x;
    const int lane = tid & 31;
    const int wid = tid >> 5;
    const int qid = lane >> 2, tg = lane & 3;
    const int r0 = (wid & 1) * 32;
    const int c0 = (wid >> 1) * 32;
    const int b  = blockIdx.y;
    const int t0 = blockIdx.x * TILE;

    const uint32_t aT = smem_u32(A_t);
    const uint32_t wB = smem_u32(Wbuf);

    issue_w2(g_wt[1], wB, tid);             // Wq in flight under x load

    const float4* xp = (const float4*)(x + ((size_t)(b * NT + t0)) * ND);
    for (int i = tid; i < 1024; i += 256) {
        int row = i >> 4, k8 = i & 15;
        x_store8(A_t, row, k8, xp[row * 32 + k8 * 2], xp[row * 32 + k8 * 2 + 1]);
    }
    if (tid < 128) {
        ksum_s[tid] = g_ksum[b * 128 + tid];
        bias_s[tid] = bq[tid];
        bias_s[128 + tid] = bo[tid];
    }
    float sn[4][2], cs[4][2];
    load_rope(t0, r0, qid, tg, sn, cs);

    float acc[2][4][4];

    // ---- Q GEMM ----
    gemm_go(aT, wB, acc, r0, c0, lane);
    __syncthreads();                        // Wbuf + A reads done
    issue_w2(g_mb[b], wB, tid);             // M_b in flight under epilogue
    rope_elu_acc(acc, bias_s, c0, tg, sn, cs);

    // ---- z from accumulators; scale acc by ZSCALE/zden (per row, head) ----
    {
        float zp[2][2][2];                   // [mt][h2][g]
        #pragma unroll
        for (int mt = 0; mt < 2; mt++)
            #pragma unroll
            for (int h2 = 0; h2 < 2; h2++)
                #pragma unroll
                for (int g = 0; g < 2; g++) {
                    float s = 0.f;
                    #pragma unroll
                    for (int n1 = 0; n1 < 2; n1++) {
                        int nt = g * 2 + n1;
                        #pragma unroll
                        for (int j = 0; j < 2; j++)
                            s = fmaf(acc[mt][nt][h2 * 2 + j],
                                     ksum_s[c0 + nt * 8 + tg * 2 + j], s);
                    }
                    zp[mt][h2][g] = s;
                }
        #pragma unroll
        for (int off = 1; off <= 2; off <<= 1)
            #pragma unroll
            for (int mt = 0; mt < 2; mt++)
                #pragma unroll
                for (int h2 = 0; h2 < 2; h2++)
                    #pragma unroll
                    for (int g = 0; g < 2; g++)
                        zp[mt][h2][g] += __shfl_xor_sync(0xffffffffu, zp[mt][h2][g], off);
        float f[2][2][2];
        #pragma unroll
        for (int mt = 0; mt < 2; mt++)
            #pragma unroll
            for (int h2 = 0; h2 < 2; h2++)
                #pragma unroll
                for (int g = 0; g < 2; g++)
                    f[mt][h2][g] = ZSCALE / (zp[mt][h2][g] + 1e-6f);
        #pragma unroll
        for (int mt = 0; mt < 2; mt++)
            #pragma unroll
            for (int nt = 0; nt < 4; nt++)
                #pragma unroll
                for (int i = 0; i < 4; i++)
                    acc[mt][nt][i] *= f[mt][i >> 1][nt >> 1];
    }

    // ---- store q_z into A tile (x dead) ----
    acc_storeH(A_t, acc, r0, c0, qid, tg);

    // ---- M GEMM: out_acc = q_z @ M (syncs publish q_z stores) ----
    gemm_go(aT, wB, acc, r0, c0, lane);

    // direct global store with bias
    {
        float* op = out + ((size_t)(b * NT + t0)) * ND;
        #pragma unroll
        for (int mt = 0; mt < 2; mt++)
            #pragma unroll
            for (int nt = 0; nt < 4; nt++)
                #pragma unroll
                for (int h2 = 0; h2 < 2; h2++) {
                    int row = r0 + mt * 16 + h2 * 8 + qid;
                    int col = c0 + nt * 8 + tg * 2;
                    *(float2*)(op + (size_t)row * ND + col) =
                        make_float2(acc[mt][nt][h2 * 2] + bias_s[128 + col],
                                    acc[mt][nt][h2 * 2 + 1] + bias_s[128 + col + 1]);
                }
    }
}

// ---------------------------------------------------------------------------
extern "C" void kernel_launch(void* const* d_in, const int* in_sizes, int n_in,
                              void* d_out, int out_size)
{
    const float* x  = (const float*)d_in[0];
    const float* Wq = (const float*)d_in[1];
    const float* bq = (const float*)d_in[2];
    const float* Wk = (const float*)d_in[3];
    const float* bk = (const float*)d_in[4];
    const float* Wv = (const float*)d_in[5];
    const float* bv = (const float*)d_in[6];
    const float* Wo = (const float*)d_in[7];
    const float* bo = (const float*)d_in[8];
    float* out = (float*)d_out;

    cudaFuncSetAttribute(la_kv,   cudaFuncAttributeMaxDynamicSharedMemorySize, KV_SMEM);
    cudaFuncSetAttribute(la_qout, cudaFuncAttributeMaxDynamicSharedMemorySize, QO_SMEM);

    la_setup<<<36, 256>>>(Wq, Wk, Wv, Wo);

    dim3 grid(NT / TILE, NB);
    la_kv<<<grid, 256, KV_SMEM>>>(x, bk, bv);
    la_red<<<NB * 8, 256>>>(Wo);
    la_qout<<<grid, 256, QO_SMEM>>>(x, bq, bo, out);
}

// round 17
// speedup vs baseline: 1.1484x; 1.0725x over previous
#include <cuda_runtime.h>
#include <cuda_fp16.h>
#include <math.h>
#include <stdint.h>

#define NB 8
#define NT 8192
#define ND 128
#define NH 8
#define TILE 64
#define NTILES 128             // NT / TILE
#define ZSCALE 1024.0f         // q·z pre-scale (cancelled by M/1024)

// ---------------- scratch (device globals; no allocs allowed) ---------------
static __device__ float g_ctx[NB * 2048];                   // [b][h*256+d*16+e]
static __device__ float g_ksum[NB * 128];                   // [b][h*16+d]
static __device__ __half g_wt[4][16384];                    // W tiles (fp16, swizzled)
static __device__ __half g_mb[NB][16384];                   // M = ctxBD@Wo / 1024 (fp16)
static __device__ float g_rope[NT * 16];                    // [t][j*2]=sin, [j*2+1]=cos

// ---------------------------------------------------------------------------
__device__ __forceinline__ void mma16816(float c[4], const uint32_t a[4],
                                         uint32_t b0, uint32_t b1) {
    asm volatile(
        "mma.sync.aligned.m16n8k16.row.col.f32.f16.f16.f32 "
        "{%0,%1,%2,%3}, {%4,%5,%6,%7}, {%8,%9}, {%0,%1,%2,%3};"
        : "+f"(c[0]), "+f"(c[1]), "+f"(c[2]), "+f"(c[3])
        : "r"(a[0]), "r"(a[1]), "r"(a[2]), "r"(a[3]), "r"(b0), "r"(b1));
}
__device__ __forceinline__ void ldsm4(uint32_t r[4], uint32_t addr) {
    asm volatile("ldmatrix.sync.aligned.m8n8.x4.shared.b16 {%0,%1,%2,%3}, [%4];"
                 : "=r"(r[0]), "=r"(r[1]), "=r"(r[2]), "=r"(r[3]) : "r"(addr));
}
__device__ __forceinline__ uint32_t smem_u32(const void* p) {
    return (uint32_t)__cvta_generic_to_shared(p);
}
__device__ __forceinline__ void cp_async16(uint32_t dst, const void* src) {
    asm volatile("cp.async.cg.shared.global [%0], [%1], 16;" :: "r"(dst), "l"(src));
}
#define CP_COMMIT() asm volatile("cp.async.commit_group;" ::: "memory")
#define CP_WAIT(n)  asm volatile("cp.async.wait_group %0;" :: "n"(n) : "memory")

// A tile layout: [rows][128 fp16 = 256B], 16B-granule XOR swizzle:
// phys_byte = row*256 + (((k>>3) ^ (row&7))<<4) + (k&7)*2.

// Stage one granule (8 consecutive k) of x: 2 float4 -> 8 fp16 (one 16B store).
__device__ __forceinline__ void x_store8(char* a, int row, int k8, float4 v0, float4 v1) {
    uint32_t off = (uint32_t)(row * 256 + ((k8 ^ (row & 7)) << 4));
    __half2 h[4];
    h[0] = __floats2half2_rn(v0.x, v0.y);
    h[1] = __floats2half2_rn(v0.z, v0.w);
    h[2] = __floats2half2_rn(v1.x, v1.y);
    h[3] = __floats2half2_rn(v1.z, v1.w);
    *(uint4*)(a + off) = *(const uint4*)h;
}

// Issue both 16KB W chunks of one W tile (two commit groups).
__device__ __forceinline__ void issue_w2(const __half* __restrict__ wsrc,
                                         uint32_t wB, int tid) {
    #pragma unroll
    for (int half = 0; half < 2; half++) {
        const char* src = (const char*)wsrc + half * 128;
        uint32_t buf = wB + (uint32_t)half * 16384;
        #pragma unroll
        for (int l = 0; l < 4; l++) {
            int i = tid + l * 256;
            int n = i >> 3, j = i & 7;
            cp_async16(buf + (uint32_t)i * 16, src + n * 256 + j * 16);
        }
        CP_COMMIT();
    }
}

// Compute 4 global ksteps (ks = half*4 + ksl): acc += A @ Wchunk.
__device__ __forceinline__ void gemm_chunk(uint32_t aT, uint32_t wbuf, int half,
                                           float acc[2][4][4], int r0, int c0, int lane) {
    const int l7 = lane & 7;
    const int am8 = ((lane >> 3) & 1) << 3;
    const int akh = lane >> 4;
    const int bm8 = ((lane >> 4) & 1) << 3;
    const int bpar = (lane >> 3) & 1;
    uint32_t arow[2], brow[2];
    int arow7[2], brow7[2];
    #pragma unroll
    for (int mt = 0; mt < 2; mt++) {
        int r = r0 + mt * 16 + am8 + l7;
        arow[mt] = (uint32_t)(r * 256); arow7[mt] = r & 7;
    }
    #pragma unroll
    for (int n2 = 0; n2 < 2; n2++) {
        int r = c0 + n2 * 16 + bm8 + l7;
        brow[n2] = (uint32_t)(r * 128); brow7[n2] = r & 7;
    }
    #pragma unroll
    for (int ksl = 0; ksl < 4; ksl++) {
        int ks = half * 4 + ksl;
        uint32_t Af[2][4], Bf[2][4];
        #pragma unroll
        for (int mt = 0; mt < 2; mt++) {
            uint32_t g = (uint32_t)(((2 * ks + akh) ^ arow7[mt]) << 4);
            ldsm4(Af[mt], aT + arow[mt] + g);
        }
        #pragma unroll
        for (int n2 = 0; n2 < 2; n2++) {
            uint32_t g = (uint32_t)(((2 * ksl + bpar) ^ brow7[n2]) << 4);
            ldsm4(Bf[n2], wbuf + brow[n2] + g);
        }
        #pragma unroll
        for (int n2 = 0; n2 < 2; n2++)
            #pragma unroll
            for (int j = 0; j < 2; j++) {
                int nt = n2 * 2 + j;
                uint32_t b0 = Bf[n2][j * 2], b1 = Bf[n2][j * 2 + 1];
                #pragma unroll
                for (int mt = 0; mt < 2; mt++)
                    mma16816(acc[mt][nt], Af[mt], b0, b1);
            }
    }
}

// Full GEMM from pre-issued chunks: waits chunk-by-chunk, computes.
__device__ __forceinline__ void gemm_go(uint32_t aT, uint32_t wB, float acc[2][4][4],
                                        int r0, int c0, int lane) {
    #pragma unroll
    for (int mt = 0; mt < 2; mt++)
        #pragma unroll
        for (int nt = 0; nt < 4; nt++)
            #pragma unroll
            for (int i = 0; i < 4; i++) acc[mt][nt][i] = 0.f;
    CP_WAIT(1);
    __syncthreads();
    gemm_chunk(aT, wB, 0, acc, r0, c0, lane);
    CP_WAIT(0);
    __syncthreads();
    gemm_chunk(aT, wB + 16384, 1, acc, r0, c0, lane);
}

// bias + RoPE + elu+1 on accumulators.
__device__ __forceinline__ void rope_elu_acc(float acc[2][4][4],
                                             const float* bias_s, int c0, int tg,
                                             const float sn[4][2], const float cs[4][2]) {
    #pragma unroll
    for (int mt = 0; mt < 2; mt++)
        #pragma unroll
        for (int t = 0; t < 2; t++)
            #pragma unroll
            for (int i = 0; i < 4; i++) {
                int ridx = mt * 2 + (i >> 1);
                int jj = i & 1;
                float x1 = acc[mt][2 * t][i]     + bias_s[c0 + t * 16 + tg * 2 + jj];
                float x2 = acc[mt][2 * t + 1][i] + bias_s[c0 + t * 16 + 8 + tg * 2 + jj];
                float s = sn[ridx][jj], c = cs[ridx][jj];
                float y1 = x1 * c - x2 * s;
                float y2 = x1 * s + x2 * c;
                acc[mt][2 * t][i]     = y1 > 0.f ? y1 + 1.f : __expf(y1);
                acc[mt][2 * t + 1][i] = y2 > 0.f ? y2 + 1.f : __expf(y2);
            }
}

// Store accumulators as fp16 tile [rows][128 fp16], 16B-granule swizzle.
__device__ __forceinline__ void acc_storeH(char* dstH, const float acc[2][4][4],
                                           int r0, int c0, int qid, int tg) {
    #pragma unroll
    for (int mt = 0; mt < 2; mt++)
        #pragma unroll
        for (int nt = 0; nt < 4; nt++)
            #pragma unroll
            for (int h2 = 0; h2 < 2; h2++) {
                int row = r0 + mt * 16 + h2 * 8 + qid;
                int col = c0 + nt * 8 + tg * 2;
                uint32_t off = (uint32_t)(row * 256 +
                    (((col >> 3) ^ (row & 7)) << 4) + (col & 7) * 2);
                *(__half2*)(dstH + off) =
                    __floats2half2_rn(acc[mt][nt][h2 * 2], acc[mt][nt][h2 * 2 + 1]);
            }
}

// Store accumulators TRANSPOSED as fp16: dstT[feature][t], rows 128B,
// phys = f*128 + (((t>>3) ^ (f&7))<<4) + (t&7)*2.
__device__ __forceinline__ void acc_storeT(char* dstT, const float acc[2][4][4],
                                           const float* bias_s, bool add_bias,
                                           int r0, int c0, int qid, int tg) {
    #pragma unroll
    for (int mt = 0; mt < 2; mt++)
        #pragma unroll
        for (int nt = 0; nt < 4; nt++)
            #pragma unroll
            for (int i = 0; i < 4; i++) {
                int t = r0 + mt * 16 + (i >> 1) * 8 + qid;
                int f = c0 + nt * 8 + tg * 2 + (i & 1);
                float v = acc[mt][nt][i];
                if (add_bias) v += bias_s[f];
                uint32_t off = (uint32_t)(f * 128 + (((t >> 3) ^ (f & 7)) << 4) + (t & 7) * 2);
                *(__half*)(dstT + off) = __float2half_rn(v);
            }
}

// Load rope tables from global.
__device__ __forceinline__ void load_rope(int t0, int r0, int qid, int tg,
                                          float sn[4][2], float cs[4][2]) {
    #pragma unroll
    for (int ridx = 0; ridx < 4; ridx++) {
        int mt = ridx >> 1, half = ridx & 1;
        int t = t0 + r0 + mt * 16 + half * 8 + qid;
        float4 v = *(const float4*)&g_rope[t * 16 + tg * 4];
        sn[ridx][0] = v.x; cs[ridx][0] = v.y;
        sn[ridx][1] = v.z; cs[ridx][1] = v.w;
    }
}

// ---------------------------------------------------------------------------
// Kernel 0: setup. Blocks 0-3: W->fp16; 4-35: rope; 36-39: zero ctx/ksum.
// ---------------------------------------------------------------------------
extern "C" __global__ void __launch_bounds__(256)
la_setup(const float* __restrict__ Wq, const float* __restrict__ Wk,
         const float* __restrict__ Wv, const float* __restrict__ Wo)
{
    if (blockIdx.x < 4) {
        const float* W = (blockIdx.x == 0) ? Wk : (blockIdx.x == 1) ? Wq
                       : (blockIdx.x == 2) ? Wv : Wo;
        __half* wh = g_wt[blockIdx.x];
        const float4* Wp = (const float4*)W;
        for (int i = threadIdx.x; i < 4096; i += 256) {
            int k = i >> 5, n4 = i & 31;
            float4 w = Wp[i];
            float vv[4] = {w.x, w.y, w.z, w.w};
            #pragma unroll
            for (int u = 0; u < 4; u++) {
                int n = n4 * 4 + u;
                uint32_t e = (uint32_t)(n * 128 + ((((k >> 3) ^ (n & 7)) << 3) | (k & 7)));
                wh[e] = __float2half_rn(vv[u]);
            }
        }
    } else if (blockIdx.x < 36) {
        const float invf[8] = {1.0f, 0.31622776601683794f, 0.1f, 0.03162277660168379f,
                               0.01f, 0.0031622776601683794f, 0.001f, 0.00031622776601683794f};
        int t = (blockIdx.x - 4) * 256 + threadIdx.x;     // 32 blocks x 256 = 8192
        float tf = (float)t;
        #pragma unroll
        for (int j = 0; j < 8; j++) {
            float s, c;
            sincosf(tf * invf[j], &s, &c);
            g_rope[t * 16 + j * 2] = s;
            g_rope[t * 16 + j * 2 + 1] = c;
        }
    } else {
        // zero accumulation scratch (fresh each graph replay)
        int base = (blockIdx.x - 36) * 4096 + threadIdx.x;
        #pragma unroll
        for (int l = 0; l < 16; l++) g_ctx[base + l * 256] = 0.f;
        if (blockIdx.x == 36) {
            #pragma unroll
            for (int l = 0; l < 4; l++) g_ksum[threadIdx.x + l * 256] = 0.f;
        }
    }
}

// ---------------------------------------------------------------------------
// Kernel 1: K, V GEMMs; transposed fp16 k/v tiles; ctx via diagonal MMA;
// direct fp32 atomics to g_ctx / g_ksum (no partial arrays).
// smem: A/vT 16K | Wbuf 32K | kT 16K | bias 1K  (~65.5K -> 3 blocks/SM)
// ---------------------------------------------------------------------------
#define KV_WB    16384
#define KV_KT    49152
#define KV_BIAS  65536
#define KV_SMEM  66560

extern "C" __global__ void __launch_bounds__(256, 3)
la_kv(const float* __restrict__ x,
      const float* __restrict__ bk, const float* __restrict__ bv)
{
    extern __shared__ char sm[];
    char* A_t = sm;
    char* kT  = sm + KV_KT;
    char* vT  = sm;                         // alias A (A dead after V GEMM)
    float* bias_s = (float*)(sm + KV_BIAS); // [2][128]: k, v

    const int tid = threadIdx.x;
    const int lane = tid & 31;
    const int wid = tid >> 5;
    const int qid = lane >> 2, tg = lane & 3;
    const int r0 = (wid & 1) * 32;
    const int c0 = (wid >> 1) * 32;
    const int b  = blockIdx.y;
    const int t0 = blockIdx.x * TILE;

    const uint32_t aT  = smem_u32(A_t);
    const uint32_t wB  = smem_u32(sm + KV_WB);
    const uint32_t kTa = smem_u32(kT);
    const uint32_t vTa = aT;

    issue_w2(g_wt[0], wB, tid);             // Wk in flight under x load

    const float4* xp = (const float4*)(x + ((size_t)(b * NT + t0)) * ND);
    for (int i = tid; i < 1024; i += 256) {
        int row = i >> 4, k8 = i & 15;
        x_store8(A_t, row, k8, xp[row * 32 + k8 * 2], xp[row * 32 + k8 * 2 + 1]);
    }
    if (tid < 128) {
        bias_s[tid]       = bk[tid];
        bias_s[128 + tid] = bv[tid];
    }
    float sn[4][2], cs[4][2];
    load_rope(t0, r0, qid, tg, sn, cs);

    float acc[2][4][4];

    // ---- K GEMM (first sync inside gemm_go also publishes A stores) ----
    gemm_go(aT, wB, acc, r0, c0, lane);
    __syncthreads();                        // all Wbuf reads done
    issue_w2(g_wt[2], wB, tid);             // Wv in flight under K epilogue
    rope_elu_acc(acc, bias_s, c0, tg, sn, cs);

    // ksum partials via register shuffles, then atomic add
    {
        float s[8];
        #pragma unroll
        for (int nt = 0; nt < 4; nt++)
            #pragma unroll
            for (int j = 0; j < 2; j++) {
                float v = 0.f;
                #pragma unroll
                for (int mt = 0; mt < 2; mt++)
                    #pragma unroll
                    for (int h2 = 0; h2 < 2; h2++)
                        v += acc[mt][nt][h2 * 2 + j];
                s[nt * 2 + j] = v;
            }
        #pragma unroll
        for (int off = 4; off <= 16; off <<= 1)
            #pragma unroll
            for (int u = 0; u < 8; u++)
                s[u] += __shfl_xor_sync(0xffffffffu, s[u], off);
        if (qid == 0) {
            #pragma unroll
            for (int nt = 0; nt < 4; nt++)
                #pragma unroll
                for (int j = 0; j < 2; j++)
                    atomicAdd(&g_ksum[b * 128 + c0 + nt * 8 + tg * 2 + j],
                              s[nt * 2 + j]);
        }
    }
    acc_storeT(kT, acc, bias_s, false, r0, c0, qid, tg);

    // ---- V GEMM ----
    gemm_go(aT, wB, acc, r0, c0, lane);
    __syncthreads();                        // all A reads done before vT overwrite
    acc_storeT(vT, acc, bias_s + 128, true, r0, c0, qid, tg);
    __syncthreads();                        // kT + vT visible

    // ---- ctx via diagonal MMA: warp = (tile = wid&3, tgrp = wid>>2) ----
    {
        const int tile = wid & 3, tgrp = wid >> 2;
        const int base = tile * 32;
        const int l7 = lane & 7;
        const int am8 = ((lane >> 3) & 1) << 3;
        const int akh = lane >> 4;
        const int bm8 = ((lane >> 4) & 1) << 3;
        const int bpar = (lane >> 3) & 1;
        float c2[2][4][4];
        #pragma unroll
        for (int mt = 0; mt < 2; mt++)
            #pragma unroll
            for (int nt = 0; nt < 4; nt++)
                #pragma unroll
                for (int i = 0; i < 4; i++) c2[mt][nt][i] = 0.f;

        #pragma unroll
        for (int ksl = 0; ksl < 2; ksl++) {
            uint32_t Af[2][4], Bf[2][4];
            #pragma unroll
            for (int mt = 0; mt < 2; mt++) {
                int r = base + mt * 16 + am8 + l7;
                uint32_t g = (uint32_t)(((tgrp * 4 + 2 * ksl + akh) ^ (r & 7)) << 4);
                ldsm4(Af[mt], kTa + (uint32_t)(r * 128) + g);
            }
            #pragma unroll
            for (int n2 = 0; n2 < 2; n2++) {
                int r = base + n2 * 16 + bm8 + l7;
                uint32_t g = (uint32_t)(((tgrp * 4 + 2 * ksl + bpar) ^ (r & 7)) << 4);
                ldsm4(Bf[n2], vTa + (uint32_t)(r * 128) + g);
            }
            #pragma unroll
            for (int n2 = 0; n2 < 2; n2++)
                #pragma unroll
                for (int j = 0; j < 2; j++) {
                    int nt = n2 * 2 + j;
                    uint32_t b0 = Bf[n2][j * 2], b1 = Bf[n2][j * 2 + 1];
                    #pragma unroll
                    for (int mt = 0; mt < 2; mt++)
                        mma16816(c2[mt][nt], Af[mt], b0, b1);
                }
        }

        // keep diagonal blocks (mt == nt>>1); atomic-accumulate to g_ctx
        float* cb = g_ctx + b * 2048;
        #pragma unroll
        for (int mt = 0; mt < 2; mt++)
            #pragma unroll
            for (int n1 = 0; n1 < 2; n1++) {
                int nt = mt * 2 + n1;
                #pragma unroll
                for (int i = 0; i < 4; i++) {
                    int head = tile * 2 + mt;
                    int d = (i >> 1) * 8 + qid;
                    int e = n1 * 8 + tg * 2 + (i & 1);
                    atomicAdd(cb + head * 256 + d * 16 + e, c2[mt][nt][i]);
                }
            }
    }
}

// ---------------------------------------------------------------------------
// Kernel 2: build M_b = ctxBD @ Wo / ZSCALE (fp16, W layout).
// grid = NB*NH blocks (block ch owns head ch of batch b), 256 threads.
// ---------------------------------------------------------------------------
extern "C" __global__ void __launch_bounds__(256)
la_red(const float* __restrict__ Wo)
{
    __shared__ float ctx_s[16][17];
    int b = blockIdx.x >> 3, ch = blockIdx.x & 7;
    {
        int d = threadIdx.x >> 4, e2 = threadIdx.x & 15;
        ctx_s[d][e2] = g_ctx[b * 2048 + ch * 256 + d * 16 + e2];
    }
    __syncthreads();

    // M rows [ch*16, ch*16+16): thread (d2, nc) computes 8 cols.
    int d2 = threadIdx.x >> 4, nc = threadIdx.x & 15;
    __half* mb = g_mb[b];
    int k = ch * 16 + d2;
    #pragma unroll
    for (int j = 0; j < 8; j++) {
        int n = nc * 8 + j;
        float m = 0.f;
        #pragma unroll
        for (int e3 = 0; e3 < 16; e3++)
            m = fmaf(ctx_s[d2][e3], Wo[(ch * 16 + e3) * 128 + n], m);
        mb[n * 128 + ((((k >> 3) ^ (n & 7)) << 3) | (k & 7))] =
            __float2half_rn(m * (1.f / ZSCALE));
    }
}

// ---------------------------------------------------------------------------
// Kernel 3: q = rope_elu(x@Wq+bq); out = (q*z*S) @ (ctxBD@Wo/S) + bo.
// smem: A 16K | Wbuf 32K | ksum .5K | bias 1K  (~50K -> 3 blocks/SM)
// ---------------------------------------------------------------------------
#define QO_WB    16384
#define QO_KSUM  49152
#define QO_BIAS  49664
#define QO_SMEM  50688

extern "C" __global__ void __launch_bounds__(256, 3)
la_qout(const float* __restrict__ x,
        const float* __restrict__ bq, const float* __restrict__ bo,
        float* __restrict__ out)
{
    extern __shared__ char sm[];
    char* A_t  = sm;
    char* Wbuf = sm + QO_WB;
    float* ksum_s = (float*)(sm + QO_KSUM);
    float* bias_s = (float*)(sm + QO_BIAS);  // [2][128]: q, o

    const int tid = threadIdx.x;
    const int lane = tid & 31;
    const int wid = tid >> 5;
    const int qid = lane >> 2, tg = lane & 3;
    const int r0 = (wid & 1) * 32;
    const int c0 = (wid >> 1) * 32;
    const int b  = blockIdx.y;
    const int t0 = blockIdx.x * TILE;

    const uint32_t aT = smem_u32(A_t);
    const uint32_t wB = smem_u32(Wbuf);

    issue_w2(g_wt[1], wB, tid);             // Wq in flight under x load

    const float4* xp = (const float4*)(x + ((size_t)(b * NT + t0)) * ND);
    for (int i = tid; i < 1024; i += 256) {
        int row = i >> 4, k8 = i & 15;
        x_store8(A_t, row, k8, xp[row * 32 + k8 * 2], xp[row * 32 + k8 * 2 + 1]);
    }
    if (tid < 128) {
        ksum_s[tid] = g_ksum[b * 128 + tid];
        bias_s[tid] = bq[tid];
        bias_s[128 + tid] = bo[tid];
    }
    float sn[4][2], cs[4][2];
    load_rope(t0, r0, qid, tg, sn, cs);

    float acc[2][4][4];

    // ---- Q GEMM ----
    gemm_go(aT, wB, acc, r0, c0, lane);
    __syncthreads();                        // Wbuf + A reads done
    issue_w2(g_mb[b], wB, tid);             // M_b in flight under epilogue
    rope_elu_acc(acc, bias_s, c0, tg, sn, cs);

    // ---- z from accumulators; scale acc by ZSCALE/zden (per row, head) ----
    {
        float zp[2][2][2];                   // [mt][h2][g]
        #pragma unroll
        for (int mt = 0; mt < 2; mt++)
            #pragma unroll
            for (int h2 = 0; h2 < 2; h2++)
                #pragma unroll
                for (int g = 0; g < 2; g++) {
                    float s = 0.f;
                    #pragma unroll
                    for (int n1 = 0; n1 < 2; n1++) {
                        int nt = g * 2 + n1;
                        #pragma unroll
                        for (int j = 0; j < 2; j++)
                            s = fmaf(acc[mt][nt][h2 * 2 + j],
                                     ksum_s[c0 + nt * 8 + tg * 2 + j], s);
                    }
                    zp[mt][h2][g] = s;
                }
        #pragma unroll
        for (int off = 1; off <= 2; off <<= 1)
            #pragma unroll
            for (int mt = 0; mt < 2; mt++)
                #pragma unroll
                for (int h2 = 0; h2 < 2; h2++)
                    #pragma unroll
                    for (int g = 0; g < 2; g++)
                        zp[mt][h2][g] += __shfl_xor_sync(0xffffffffu, zp[mt][h2][g], off);
        float f[2][2][2];
        #pragma unroll
        for (int mt = 0; mt < 2; mt++)
            #pragma unroll
            for (int h2 = 0; h2 < 2; h2++)
                #pragma unroll
                for (int g = 0; g < 2; g++)
                    f[mt][h2][g] = ZSCALE / (zp[mt][h2][g] + 1e-6f);
        #pragma unroll
        for (int mt = 0; mt < 2; mt++)
            #pragma unroll
            for (int nt = 0; nt < 4; nt++)
                #pragma unroll
                for (int i = 0; i < 4; i++)
                    acc[mt][nt][i] *= f[mt][i >> 1][nt >> 1];
    }

    // ---- store q_z into A tile (x dead) ----
    acc_storeH(A_t, acc, r0, c0, qid, tg);

    // ---- M GEMM: out_acc = q_z @ M (syncs publish q_z stores) ----
    gemm_go(aT, wB, acc, r0, c0, lane);

    // direct global store with bias
    {
        float* op = out + ((size_t)(b * NT + t0)) * ND;
        #pragma unroll
        for (int mt = 0; mt < 2; mt++)
            #pragma unroll
            for (int nt = 0; nt < 4; nt++)
                #pragma unroll
                for (int h2 = 0; h2 < 2; h2++) {
                    int row = r0 + mt * 16 + h2 * 8 + qid;
                    int col = c0 + nt * 8 + tg * 2;
                    *(float2*)(op + (size_t)row * ND + col) =
                        make_float2(acc[mt][nt][h2 * 2] + bias_s[128 + col],
                                    acc[mt][nt][h2 * 2 + 1] + bias_s[128 + col + 1]);
                }
    }
}

// ---------------------------------------------------------------------------
extern "C" void kernel_launch(void* const* d_in, const int* in_sizes, int n_in,
                              void* d_out, int out_size)
{
    const float* x  = (const float*)d_in[0];
    const float* Wq = (const float*)d_in[1];
    const float* bq = (const float*)d_in[2];
    const float* Wk = (const float*)d_in[3];
    const float* bk = (const float*)d_in[4];
    const float* Wv = (const float*)d_in[5];
    const float* bv = (const float*)d_in[6];
    const float* Wo = (const float*)d_in[7];
    const float* bo = (const float*)d_in[8];
    float* out = (float*)d_out;

    cudaFuncSetAttribute(la_kv,   cudaFuncAttributeMaxDynamicSharedMemorySize, KV_SMEM);
    cudaFuncSetAttribute(la_qout, cudaFuncAttributeMaxDynamicSharedMemorySize, QO_SMEM);

    la_setup<<<40, 256>>>(Wq, Wk, Wv, Wo);

    dim3 grid(NT / TILE, NB);
    la_kv<<<grid, 256, KV_SMEM>>>(x, bk, bv);
    la_red<<<NB * NH, 256>>>(Wo);
    la_qout<<<grid, 256, QO_SMEM>>>(x, bq, bo, out);
}